// round 14
// baseline (speedup 1.0000x reference)
#include <cuda_runtime.h>
#include <cuda_bf16.h>
#include <math.h>
#include <stdint.h>

// Problem constants
#define B_   64
#define T_   512
#define I_   256
#define D_   1024
#define M_   128
#define NTHREADS 256
#define KSPLIT 8
#define KSLICE 128
#define NTILE  64

// ---------------------------------------------------------------------------
// Device globals (allocation-free scratch)
// ---------------------------------------------------------------------------
__device__ float g_E[T_ * B_ * D_];                          // embed [t][b][d]
__device__ __align__(16) __nv_bfloat16 g_s_hi[M_ * D_];      // rows 0-63 fwd, 64-127 bwd
__device__ __align__(16) __nv_bfloat16 g_s_lo[M_ * D_];
__device__ __align__(16) __nv_bfloat16 g_Wt_hi[D_ * D_];     // W^T [n][k]
__device__ __align__(16) __nv_bfloat16 g_Wt_lo[D_ * D_];
__device__ __align__(16) __nv_bfloat16 g_in_hi[B_ * T_ * I_];
__device__ __align__(16) __nv_bfloat16 g_in_lo[B_ * T_ * I_];
__device__ __align__(16) __nv_bfloat16 g_Ut_hi[D_ * I_];
__device__ __align__(16) __nv_bfloat16 g_Ut_lo[D_ * I_];
__device__ float g_part[2][KSPLIT][B_][D_];                  // per-chain split-K partials
// counters per chain: c1[0..7] | c2lo[0..7] | c2hi[0..7], each on own 128B line
#define NCNT (2 * 24 * 32)
__device__ unsigned g_cnt[NCNT];

// ---------------------------------------------------------------------------
// mma.sync bf16 + ldmatrix (sm_80 baseline)
// ---------------------------------------------------------------------------
__device__ __forceinline__ void mma_bf16(float* c, const uint32_t* a, const uint32_t* b) {
    asm volatile(
        "mma.sync.aligned.m16n8k16.row.col.f32.bf16.bf16.f32 "
        "{%0,%1,%2,%3}, {%4,%5,%6,%7}, {%8,%9}, {%0,%1,%2,%3};"
        : "+f"(c[0]), "+f"(c[1]), "+f"(c[2]), "+f"(c[3])
        : "r"(a[0]), "r"(a[1]), "r"(a[2]), "r"(a[3]), "r"(b[0]), "r"(b[1]));
}

__device__ __forceinline__ void ldm_x4(uint32_t* r, uint32_t saddr) {
    asm volatile(
        "ldmatrix.sync.aligned.m8n8.x4.shared.b16 {%0,%1,%2,%3}, [%4];"
        : "=r"(r[0]), "=r"(r[1]), "=r"(r[2]), "=r"(r[3]) : "r"(saddr));
}

#define BAR_ARRIVE(ptr) \
    asm volatile("red.release.gpu.global.add.u32 [%0], 1;" :: "l"(ptr) : "memory")

#define BAR_SPIN(ptr, tgt) do { \
    unsigned _v; \
    do { asm volatile("ld.acquire.gpu.global.u32 %0, [%1];" \
                      : "=r"(_v) : "l"(ptr) : "memory"); } while (_v < (tgt)); \
} while (0)

// ---------------------------------------------------------------------------
// Split kernels (one-time prep). inp_split also zeroes counters.
// ---------------------------------------------------------------------------
__global__ void inp_split_kernel(const float* __restrict__ inp) {
    if (blockIdx.x == 0) {
        for (int i = threadIdx.x; i < NCNT; i += blockDim.x) g_cnt[i] = 0;
    }
    int idx = blockIdx.x * blockDim.x + threadIdx.x;
    const int N4 = B_ * T_ * I_ / 4;
    if (idx >= N4) return;
    float4 a = ((const float4*)inp)[idx];
    __nv_bfloat16 h0 = __float2bfloat16(a.x), h1 = __float2bfloat16(a.y);
    __nv_bfloat16 h2 = __float2bfloat16(a.z), h3 = __float2bfloat16(a.w);
    __nv_bfloat16 l0 = __float2bfloat16(a.x - __bfloat162float(h0));
    __nv_bfloat16 l1 = __float2bfloat16(a.y - __bfloat162float(h1));
    __nv_bfloat16 l2 = __float2bfloat16(a.z - __bfloat162float(h2));
    __nv_bfloat16 l3 = __float2bfloat16(a.w - __bfloat162float(h3));
    uint2 ph, pl;
    ph.x = ((uint32_t)__bfloat16_as_ushort(h1) << 16) | __bfloat16_as_ushort(h0);
    ph.y = ((uint32_t)__bfloat16_as_ushort(h3) << 16) | __bfloat16_as_ushort(h2);
    pl.x = ((uint32_t)__bfloat16_as_ushort(l1) << 16) | __bfloat16_as_ushort(l0);
    pl.y = ((uint32_t)__bfloat16_as_ushort(l3) << 16) | __bfloat16_as_ushort(l2);
    *(uint2*)&g_in_hi[idx * 4] = ph;
    *(uint2*)&g_in_lo[idx * 4] = pl;
}

__global__ void ut_split_kernel(const float* __restrict__ U) {
    const int d = blockIdx.x;
    for (int i = threadIdx.x; i < I_; i += 256) {
        float u = U[(size_t)i * D_ + d];
        __nv_bfloat16 h = __float2bfloat16(u);
        g_Ut_hi[(size_t)d * I_ + i] = h;
        g_Ut_lo[(size_t)d * I_ + i] = __float2bfloat16(u - __bfloat162float(h));
    }
}

__global__ void wt_split_kernel(const float* __restrict__ W) {
    const int n = blockIdx.x;
    for (int k = threadIdx.x; k < D_; k += 256) {
        float w = W[(size_t)k * D_ + n];
        __nv_bfloat16 h = __float2bfloat16(w);
        g_Wt_hi[(size_t)n * D_ + k] = h;
        g_Wt_lo[(size_t)n * D_ + k] = __float2bfloat16(w - __bfloat162float(h));
    }
}

// ---------------------------------------------------------------------------
// RNN smem layout: bf16 rows of 128 elems, stride 68 words (conflict-free)
// ---------------------------------------------------------------------------
#define SROW 68
#define RA_HI_W 0
#define RA_LO_W (64 * SROW)
#define RB_HI_W (128 * SROW)
#define RB_LO_W (192 * SROW)
#define SMEM_BYTES_RNN (256 * SROW * 4)   // 69632 B, occ 2

// ---------------------------------------------------------------------------
// Embed smem layout: K-chunks of 64 bf16 (128B rows, stride 36 words),
// 2 buffers for cp.async double-buffering. 110592 B total, occ 2.
// ---------------------------------------------------------------------------
#define EROW 36
#define EA_HI_W 0
#define EA_LO_W (128 * EROW)
#define EB_HI_W (256 * EROW)
#define EB_LO_W (320 * EROW)
#define E_BUF_W (384 * EROW)
#define SMEM_BYTES_EMB (2 * E_BUF_W * 4)  // 110592 B

// ---------------------------------------------------------------------------
// Embed (tensor core, pipelined K): E[t][b][:] = inp[b,t,:] @ U / 16 + bias
// grid = (16 ntile, 256 mtile); mtile -> b = mt>>2, t0 = (mt&3)*128. M=128.
// 4 K-chunks of 64, double-buffered cp.async.
// ---------------------------------------------------------------------------
__global__ void __launch_bounds__(NTHREADS, 2) embed_mma_kernel(
        const float* __restrict__ bias) {
    extern __shared__ __align__(16) uint32_t smw[];
    const int tid = threadIdx.x;
    const int wid = tid >> 5;
    const int lt  = tid & 31;
    const int g4  = lt >> 2;
    const int q4  = lt & 3;
    const int nb  = blockIdx.x;
    const int mt_idx = blockIdx.y;
    const int n0  = nb * NTILE;
    const int b   = mt_idx >> 2;
    const int t0  = (mt_idx & 3) << 7;
    const size_t row0 = (size_t)b * T_ + t0;

    const int m_base = (wid >> 1) * 32;
    const int n_base = (wid & 1) * 32;

    const int a_r  = lt & 15;
    const int a_cw = ((lt >> 4) & 1) * 4;
    const int b_r  = ((lt >> 4) & 1) * 8 + (lt & 7);
    const int b_cw = ((lt >> 3) & 1) * 4;

    uint32_t smem_b32 = (uint32_t)__cvta_generic_to_shared(smw);

    float acc[2][4][4];
    #pragma unroll
    for (int mt = 0; mt < 2; mt++)
        #pragma unroll
        for (int nt = 0; nt < 4; nt++)
            #pragma unroll
            for (int j = 0; j < 4; j++) acc[mt][nt][j] = 0.f;

    // prefetch: loads K-chunk (i0 = c*64) into buffer bw (16B cp.async only)
    #define E_PREFETCH(c_, bw_)                                                \
    {                                                                          \
        const int i0 = (c_) * 64;                                             \
        const uint32_t bufb = smem_b32 + (bw_) * E_BUF_W * 4;                  \
        /* A: 128 rows x 64 cols x 2 planes = 2048 x 16B chunks, 8/thread */   \
        _Pragma("unroll")                                                      \
        for (int i = 0; i < 8; i++) {                                          \
            int idx = i * 256 + tid;                                           \
            int ch  = idx & 7;                                                 \
            int r   = (idx >> 3) & 127;                                        \
            int hl  = idx >> 10;                                               \
            const __nv_bfloat16* src = hl ? g_in_lo : g_in_hi;                 \
            uint32_t dst = bufb + ((hl ? EA_LO_W : EA_HI_W) + r * EROW + ch * 4) * 4; \
            const char* g = (const char*)(src + (row0 + r) * I_ + i0 + ch * 8);\
            asm volatile("cp.async.cg.shared.global [%0], [%1], 16;\n" :: "r"(dst), "l"(g)); \
        }                                                                      \
        /* B: 64 rows x 64 cols x 2 planes = 1024 x 16B chunks, 4/thread */    \
        _Pragma("unroll")                                                      \
        for (int i = 0; i < 4; i++) {                                          \
            int idx = i * 256 + tid;                                           \
            int ch  = idx & 7;                                                 \
            int r   = (idx >> 3) & 63;                                         \
            int hl  = idx >> 9;                                                \
            const __nv_bfloat16* src = hl ? g_Ut_lo : g_Ut_hi;                 \
            uint32_t dst = bufb + ((hl ? EB_LO_W : EB_HI_W) + r * EROW + ch * 4) * 4; \
            const char* g = (const char*)(src + (size_t)(n0 + r) * I_ + i0 + ch * 8); \
            asm volatile("cp.async.cg.shared.global [%0], [%1], 16;\n" :: "r"(dst), "l"(g)); \
        }                                                                      \
        asm volatile("cp.async.commit_group;\n");                              \
    }

    E_PREFETCH(0, 0);

    for (int c = 0; c < 4; c++) {
        const int buf = c & 1;
        if (c + 1 < 4) {
            E_PREFETCH(c + 1, (c + 1) & 1);
            asm volatile("cp.async.wait_group 1;\n");
        } else {
            asm volatile("cp.async.wait_group 0;\n");
        }
        __syncthreads();

        const uint32_t bufb = smem_b32 + buf * E_BUF_W * 4;
        #pragma unroll
        for (int kc = 0; kc < 4; kc++) {
            const int kw = kc * 8;
            uint32_t a_hi[2][4], a_lo[2][4], b_hi[2][4], b_lo[2][4];
            #pragma unroll
            for (int mt = 0; mt < 2; mt++) {
                int row = m_base + mt * 16 + a_r;
                ldm_x4(a_hi[mt], bufb + (EA_HI_W + row * EROW + kw + a_cw) * 4);
                ldm_x4(a_lo[mt], bufb + (EA_LO_W + row * EROW + kw + a_cw) * 4);
            }
            #pragma unroll
            for (int np = 0; np < 2; np++) {
                int row = n_base + np * 16 + b_r;
                ldm_x4(b_hi[np], bufb + (EB_HI_W + row * EROW + kw + b_cw) * 4);
                ldm_x4(b_lo[np], bufb + (EB_LO_W + row * EROW + kw + b_cw) * 4);
            }
            #pragma unroll
            for (int mt = 0; mt < 2; mt++)
                #pragma unroll
                for (int np = 0; np < 2; np++)
                    #pragma unroll
                    for (int h = 0; h < 2; h++) {
                        mma_bf16(acc[mt][np * 2 + h], a_hi[mt], &b_hi[np][h * 2]);
                        mma_bf16(acc[mt][np * 2 + h], a_hi[mt], &b_lo[np][h * 2]);
                        mma_bf16(acc[mt][np * 2 + h], a_lo[mt], &b_hi[np][h * 2]);
                    }
        }
        __syncthreads();   // protect buffer reuse
    }

    const float inv16 = 0.0625f;
    #pragma unroll
    for (int nt = 0; nt < 4; nt++) {
        const int C = n0 + n_base + nt * 8 + q4 * 2;
        float2 bv = *(const float2*)&bias[C];
        #pragma unroll
        for (int mt = 0; mt < 2; mt++) {
            const int R = m_base + mt * 16 + g4;
            float2 o0 = make_float2(acc[mt][nt][0] * inv16 + bv.x,
                                    acc[mt][nt][1] * inv16 + bv.y);
            float2 o1 = make_float2(acc[mt][nt][2] * inv16 + bv.x,
                                    acc[mt][nt][3] * inv16 + bv.y);
            *(float2*)&g_E[((size_t)(t0 + R) * B_ + b) * D_ + C]     = o0;
            *(float2*)&g_E[((size_t)(t0 + R + 8) * B_ + b) * D_ + C] = o1;
        }
    }
}

// ---------------------------------------------------------------------------
// s_0 = erf(E_first), split into bf16 hi/lo
// ---------------------------------------------------------------------------
__global__ void s0_kernel() {
    int idx = blockIdx.x * blockDim.x + threadIdx.x;
    int m = idx >> 10;
    int d = idx & 1023;
    float e = (m < B_) ? g_E[(size_t)0 * (B_ * D_) + m * D_ + d]
                       : g_E[(size_t)(T_ - 1) * (B_ * D_) + (m - B_) * D_ + d];
    float s = erff(e);
    __nv_bfloat16 h = __float2bfloat16(s);
    g_s_hi[idx] = h;
    g_s_lo[idx] = __float2bfloat16(s - __bfloat162float(h));
}

// ---------------------------------------------------------------------------
// Persistent recurrence kernel: 2 independent chains, 256 co-resident CTAs.
// Barrier 1 (fan-in 16): arrive c1[nb>>1], wait c1[kb]  (after GEMM).
// Reduce:   CTA (nb,kb) -> rows [nb*4,+4) x cols [kb*128,+128).
// Barrier 2 split lo/hi: s rows 0-31 <- nb 0-7 arrive c2lo[kb];
//   rows 32-63 <- nb 8-15 arrive c2hi[kb]. Consumer (top of next step) spins
//   lo, issues lo A-loads, spins hi under their flight, issues hi, one wait.
// ---------------------------------------------------------------------------
__global__ void __launch_bounds__(NTHREADS, 2) rnn_kernel() {
    extern __shared__ __align__(16) uint32_t smw[];
    const int tid   = threadIdx.x;
    const int wid   = tid >> 5;
    const int lt    = tid & 31;
    const int g4    = lt >> 2;
    const int q4    = lt & 3;
    const int bid   = blockIdx.x;
    const int chain = bid >> 7;
    const int lbid  = bid & 127;
    const int nb    = lbid & 15;
    const int kb    = lbid >> 4;
    const int n0    = nb * NTILE;
    const int k0    = kb * KSLICE;
    const int srow0 = chain * B_;

    const int m_base = (wid >> 1) * 16;
    const int n_base = (wid & 1) * 32;

    const int a_r  = lt & 15;
    const int a_cw = ((lt >> 4) & 1) * 4;
    const int b_r  = ((lt >> 4) & 1) * 8 + (lt & 7);
    const int b_cw = ((lt >> 3) & 1) * 4;

    uint32_t smem_b32 = (uint32_t)__cvta_generic_to_shared(smw);

    // ---- Preload B = W^T slice (constant across steps) ----
    #pragma unroll
    for (int hl = 0; hl < 2; hl++) {
        const __nv_bfloat16* src = hl ? g_Wt_lo : g_Wt_hi;
        const int base_w = hl ? RB_LO_W : RB_HI_W;
        #pragma unroll
        for (int i = 0; i < 4; i++) {
            int idx = i * 256 + tid;
            int r   = idx >> 4;
            int ch  = idx & 15;
            uint32_t dst = smem_b32 + (base_w + r * SROW + ch * 4) * 4;
            const char* g = (const char*)(src + (size_t)(n0 + r) * D_ + k0) + ch * 16;
            asm volatile("cp.async.cg.shared.global [%0], [%1], 16;\n" :: "r"(dst), "l"(g));
        }
    }
    asm volatile("cp.async.commit_group;\n");
    asm volatile("cp.async.wait_group 0;\n");
    __syncthreads();

    // ldmatrix base addresses
    const uint32_t ah = smem_b32 + (RA_HI_W + (m_base + a_r) * SROW + a_cw) * 4;
    const uint32_t al = smem_b32 + (RA_LO_W + (m_base + a_r) * SROW + a_cw) * 4;
    uint32_t bh[2], bl[2];
    #pragma unroll
    for (int np = 0; np < 2; np++) {
        int row = n_base + np * 16 + b_r;
        bh[np] = smem_b32 + (RB_HI_W + row * SROW + b_cw) * 4;
        bl[np] = smem_b32 + (RB_LO_W + row * SROW + b_cw) * 4;
    }

    // reduce assignment: rows [nb*4,+4) x cols [kb*128,+128), float2/thread
    const int r_lrow = nb * 4 + (tid >> 6);
    const int r_d    = k0 + (tid & 63) * 2;

    // counters
    unsigned* const c1_arr = &g_cnt[(chain * 24 + (nb >> 1)) * 32];
    unsigned* const c1_wat = &g_cnt[(chain * 24 + kb) * 32];
    unsigned* const c2lo   = &g_cnt[(chain * 24 + 8 + kb) * 32];
    unsigned* const c2hi   = &g_cnt[(chain * 24 + 16 + kb) * 32];
    unsigned* const my_c2  = (nb < 8) ? c2lo : c2hi;

    const __nv_bfloat16* const s_hi = g_s_hi + (size_t)srow0 * D_;
    const __nv_bfloat16* const s_lo = g_s_lo + (size_t)srow0 * D_;

    // A half load: rows [half*32, +32), both planes; 16B chunks, 4/thread
    #define LOAD_A_HALF(half_)                                                 \
    {                                                                          \
        _Pragma("unroll")                                                      \
        for (int i = 0; i < 4; i++) {                                          \
            int idx = i * 256 + tid;          /* 0..1023 */                    \
            int ch  = idx & 15;                                                \
            int r   = (half_) * 32 + ((idx >> 4) & 31);                        \
            int hl  = idx >> 9;                                                \
            const __nv_bfloat16* src = hl ? s_lo : s_hi;                       \
            uint32_t dst = smem_b32 + ((hl ? RA_LO_W : RA_HI_W) + r * SROW + ch * 4) * 4; \
            const char* g = (const char*)(src + (size_t)r * D_ + k0) + ch * 16;\
            asm volatile("cp.async.cg.shared.global [%0], [%1], 16;\n" :: "r"(dst), "l"(g)); \
        }                                                                      \
    }

    for (int t = 0; t < T_ - 1; t++) {
        // ---- wait lo half of s_t (producers nb 0-7 of my kb), then load ----
        if (tid == 0) BAR_SPIN(c2lo, 8u * (unsigned)t);
        __syncthreads();
        LOAD_A_HALF(0);
        asm volatile("cp.async.commit_group;\n");

        // ---- spin hi under lo-load flight, then load hi ----
        if (tid == 0) BAR_SPIN(c2hi, 8u * (unsigned)t);
        __syncthreads();
        LOAD_A_HALF(1);
        asm volatile("cp.async.commit_group;\n");

        // E prefetch for this step's reduce share
        const int te = chain ? (T_ - 2 - t) : (t + 1);
        const float2 e2 = *(const float2*)&g_E[((size_t)te * B_ + r_lrow) * D_ + r_d];

        asm volatile("cp.async.wait_group 0;\n");
        __syncthreads();

        // ---- GEMM: C[16x32/warp] = A_hi*B_hi + A_hi*B_lo + A_lo*B_hi ----
        float acc[4][4];
        #pragma unroll
        for (int j = 0; j < 4; j++)
            #pragma unroll
            for (int q = 0; q < 4; q++) acc[j][q] = 0.f;

        #pragma unroll 2
        for (int kc = 0; kc < 8; kc++) {
            const uint32_t koff = kc * 32;
            uint32_t a_hi[4], a_lo[4], b_hi[2][4], b_lo[2][4];
            ldm_x4(a_hi, ah + koff);
            ldm_x4(a_lo, al + koff);
            #pragma unroll
            for (int np = 0; np < 2; np++) {
                ldm_x4(b_hi[np], bh[np] + koff);
                ldm_x4(b_lo[np], bl[np] + koff);
            }
            #pragma unroll
            for (int np = 0; np < 2; np++)
                #pragma unroll
                for (int h = 0; h < 2; h++) {
                    mma_bf16(acc[np * 2 + h], a_hi, &b_hi[np][h * 2]);
                    mma_bf16(acc[np * 2 + h], a_hi, &b_lo[np][h * 2]);
                    mma_bf16(acc[np * 2 + h], a_lo, &b_hi[np][h * 2]);
                }
        }

        // ---- Write split-K partials ----
        {
            const int R = m_base + g4;
            #pragma unroll
            for (int j = 0; j < 4; j++) {
                const int C = n0 + n_base + j * 8 + q4 * 2;
                *(float2*)&g_part[chain][kb][R][C]     = make_float2(acc[j][0], acc[j][1]);
                *(float2*)&g_part[chain][kb][R + 8][C] = make_float2(acc[j][2], acc[j][3]);
            }
        }

        // ---- Barrier 1 (fan-in 16): partials for my reduce cols ready ----
        __syncthreads();
        if (tid == 0) {
            BAR_ARRIVE(c1_arr);
            BAR_SPIN(c1_wat, 16u * (unsigned)(t + 1));
        }
        __syncthreads();

        // ---- Reduce: c = sum/32, s_{t+1} = erf(E + c), split to bf16 ----
        {
            float2 sum = {0.f, 0.f};
            #pragma unroll
            for (int kk = 0; kk < KSPLIT; kk++) {
                float2 p = __ldcg((const float2*)&g_part[chain][kk][r_lrow][r_d]);
                sum.x += p.x; sum.y += p.y;
            }
            float s0v = erff(e2.x + sum.x * 0.03125f);
            float s1v = erff(e2.y + sum.y * 0.03125f);
            __nv_bfloat16 h0 = __float2bfloat16(s0v);
            __nv_bfloat16 h1 = __float2bfloat16(s1v);
            __nv_bfloat16 l0 = __float2bfloat16(s0v - __bfloat162float(h0));
            __nv_bfloat16 l1 = __float2bfloat16(s1v - __bfloat162float(h1));
            uint32_t ph = ((uint32_t)__bfloat16_as_ushort(h1) << 16) | __bfloat16_as_ushort(h0);
            uint32_t pl = ((uint32_t)__bfloat16_as_ushort(l1) << 16) | __bfloat16_as_ushort(l0);
            *(uint32_t*)&g_s_hi[(size_t)(srow0 + r_lrow) * D_ + r_d] = ph;
            *(uint32_t*)&g_s_lo[(size_t)(srow0 + r_lrow) * D_ + r_d] = pl;
        }

        // ---- Arrive my half of barrier 2 (wait happens at top of next step)
        __syncthreads();
        if (tid == 0) BAR_ARRIVE(my_c2);
    }
}

// ---------------------------------------------------------------------------
// Output head
// ---------------------------------------------------------------------------
__global__ void out_kernel(const float* __restrict__ v, float* __restrict__ out) {
    const int b   = blockIdx.x;
    const int tid = threadIdx.x;
    float sum = 0.f;
    for (int d = tid; d < D_; d += 256) {
        float sf = __bfloat162float(g_s_hi[b * D_ + d]) + __bfloat162float(g_s_lo[b * D_ + d]);
        float sb = __bfloat162float(g_s_hi[(B_ + b) * D_ + d]) + __bfloat162float(g_s_lo[(B_ + b) * D_ + d]);
        sum += sf * v[d] + sb * v[D_ + d];
    }
    __shared__ float red[256];
    red[tid] = sum;
    __syncthreads();
    #pragma unroll
    for (int s = 128; s > 0; s >>= 1) {
        if (tid < s) red[tid] += red[tid + s];
        __syncthreads();
    }
    if (tid == 0) out[b] = red[0] * 0.03125f;
}

// ---------------------------------------------------------------------------
// kernel_launch: graph-capturable (kernel launches only)
// ---------------------------------------------------------------------------
extern "C" void kernel_launch(void* const* d_in, const int* in_sizes, int n_in,
                              void* d_out, int out_size) {
    const float* inp  = (const float*)d_in[0];
    const float* W    = (const float*)d_in[1];
    const float* U    = (const float*)d_in[2];
    const float* bias = (const float*)d_in[3];
    const float* v    = (const float*)d_in[4];
    float* out        = (float*)d_out;

    static bool attr_set = false;
    if (!attr_set) {
        cudaFuncSetAttribute(rnn_kernel, cudaFuncAttributeMaxDynamicSharedMemorySize, SMEM_BYTES_RNN);
        cudaFuncSetAttribute(embed_mma_kernel, cudaFuncAttributeMaxDynamicSharedMemorySize, SMEM_BYTES_EMB);
        attr_set = true;
    }

    inp_split_kernel<<<(B_ * T_ * I_ / 4 + 255) / 256, 256>>>(inp);
    ut_split_kernel<<<D_, 256>>>(U);
    wt_split_kernel<<<D_, 256>>>(W);
    embed_mma_kernel<<<dim3(16, 256), NTHREADS, SMEM_BYTES_EMB>>>(bias);
    s0_kernel<<<512, 256>>>();
    rnn_kernel<<<256, NTHREADS, SMEM_BYTES_RNN>>>();
    out_kernel<<<B_, 256>>>(v, out);
}

// round 15
// speedup vs baseline: 1.0636x; 1.0636x over previous
#include <cuda_runtime.h>
#include <cuda_bf16.h>
#include <math.h>
#include <stdint.h>

// Problem constants
#define B_   64
#define T_   512
#define I_   256
#define D_   1024
#define M_   128
#define NTHREADS 256
#define KSPLIT 8
#define KSLICE 128
#define NTILE  64

// ---------------------------------------------------------------------------
// Device globals (allocation-free scratch)
// ---------------------------------------------------------------------------
__device__ float g_E[T_ * B_ * D_];                          // embed [t][b][d]
__device__ __align__(16) __nv_bfloat16 g_s_hi[M_ * D_];      // rows 0-63 fwd, 64-127 bwd
__device__ __align__(16) __nv_bfloat16 g_s_lo[M_ * D_];
__device__ __align__(16) __nv_bfloat16 g_Wt_hi[D_ * D_];     // W^T [n][k]
__device__ __align__(16) __nv_bfloat16 g_Wt_lo[D_ * D_];
__device__ __align__(16) __nv_bfloat16 g_in_hi[B_ * T_ * I_];
__device__ __align__(16) __nv_bfloat16 g_in_lo[B_ * T_ * I_];
__device__ __align__(16) __nv_bfloat16 g_Ut_hi[D_ * I_];
__device__ __align__(16) __nv_bfloat16 g_Ut_lo[D_ * I_];
__device__ float g_part[2][KSPLIT][B_][D_];                  // per-chain split-K partials
// counters: [chain][type(c1,c2)][8 groups][32-word pad]   (R9 layout)
#define NCNT (2 * 2 * 8 * 32)
__device__ unsigned g_cnt[NCNT];

// ---------------------------------------------------------------------------
// mma.sync bf16 + ldmatrix (sm_80 baseline)
// ---------------------------------------------------------------------------
__device__ __forceinline__ void mma_bf16(float* c, const uint32_t* a, const uint32_t* b) {
    asm volatile(
        "mma.sync.aligned.m16n8k16.row.col.f32.bf16.bf16.f32 "
        "{%0,%1,%2,%3}, {%4,%5,%6,%7}, {%8,%9}, {%0,%1,%2,%3};"
        : "+f"(c[0]), "+f"(c[1]), "+f"(c[2]), "+f"(c[3])
        : "r"(a[0]), "r"(a[1]), "r"(a[2]), "r"(a[3]), "r"(b[0]), "r"(b[1]));
}

__device__ __forceinline__ void ldm_x4(uint32_t* r, uint32_t saddr) {
    asm volatile(
        "ldmatrix.sync.aligned.m8n8.x4.shared.b16 {%0,%1,%2,%3}, [%4];"
        : "=r"(r[0]), "=r"(r[1]), "=r"(r[2]), "=r"(r[3]) : "r"(saddr));
}

#define BAR_ARRIVE(ptr) \
    asm volatile("red.release.gpu.global.add.u32 [%0], 1;" :: "l"(ptr) : "memory")

#define BAR_SPIN(ptr, tgt) do { \
    unsigned _v; \
    do { asm volatile("ld.acquire.gpu.global.u32 %0, [%1];" \
                      : "=r"(_v) : "l"(ptr) : "memory"); } while (_v < (tgt)); \
} while (0)

// ---------------------------------------------------------------------------
// Split kernels (one-time prep). inp_split also zeroes counters.
// ---------------------------------------------------------------------------
__global__ void inp_split_kernel(const float* __restrict__ inp) {
    if (blockIdx.x == 0) {
        for (int i = threadIdx.x; i < NCNT; i += blockDim.x) g_cnt[i] = 0;
    }
    int idx = blockIdx.x * blockDim.x + threadIdx.x;
    const int N4 = B_ * T_ * I_ / 4;
    if (idx >= N4) return;
    float4 a = ((const float4*)inp)[idx];
    __nv_bfloat16 h0 = __float2bfloat16(a.x), h1 = __float2bfloat16(a.y);
    __nv_bfloat16 h2 = __float2bfloat16(a.z), h3 = __float2bfloat16(a.w);
    __nv_bfloat16 l0 = __float2bfloat16(a.x - __bfloat162float(h0));
    __nv_bfloat16 l1 = __float2bfloat16(a.y - __bfloat162float(h1));
    __nv_bfloat16 l2 = __float2bfloat16(a.z - __bfloat162float(h2));
    __nv_bfloat16 l3 = __float2bfloat16(a.w - __bfloat162float(h3));
    uint2 ph, pl;
    ph.x = ((uint32_t)__bfloat16_as_ushort(h1) << 16) | __bfloat16_as_ushort(h0);
    ph.y = ((uint32_t)__bfloat16_as_ushort(h3) << 16) | __bfloat16_as_ushort(h2);
    pl.x = ((uint32_t)__bfloat16_as_ushort(l1) << 16) | __bfloat16_as_ushort(l0);
    pl.y = ((uint32_t)__bfloat16_as_ushort(l3) << 16) | __bfloat16_as_ushort(l2);
    *(uint2*)&g_in_hi[idx * 4] = ph;
    *(uint2*)&g_in_lo[idx * 4] = pl;
}

__global__ void ut_split_kernel(const float* __restrict__ U) {
    const int d = blockIdx.x;
    for (int i = threadIdx.x; i < I_; i += 256) {
        float u = U[(size_t)i * D_ + d];
        __nv_bfloat16 h = __float2bfloat16(u);
        g_Ut_hi[(size_t)d * I_ + i] = h;
        g_Ut_lo[(size_t)d * I_ + i] = __float2bfloat16(u - __bfloat162float(h));
    }
}

__global__ void wt_split_kernel(const float* __restrict__ W) {
    const int n = blockIdx.x;
    for (int k = threadIdx.x; k < D_; k += 256) {
        float w = W[(size_t)k * D_ + n];
        __nv_bfloat16 h = __float2bfloat16(w);
        g_Wt_hi[(size_t)n * D_ + k] = h;
        g_Wt_lo[(size_t)n * D_ + k] = __float2bfloat16(w - __bfloat162float(h));
    }
}

// ---------------------------------------------------------------------------
// RNN smem layout: bf16 rows of 128 elems, stride 68 words (conflict-free)
// ---------------------------------------------------------------------------
#define SROW 68
#define RA_HI_W 0
#define RA_LO_W (64 * SROW)
#define RB_HI_W (128 * SROW)
#define RB_LO_W (192 * SROW)
#define SMEM_BYTES_RNN (256 * SROW * 4)   // 69632 B, occ 2

// ---------------------------------------------------------------------------
// Embed smem layout: K-chunks of 64 bf16 (128B rows, stride 36 words),
// 2 buffers for cp.async double-buffering. 110592 B total, occ 2.
// ---------------------------------------------------------------------------
#define EROW 36
#define EA_HI_W 0
#define EA_LO_W (128 * EROW)
#define EB_HI_W (256 * EROW)
#define EB_LO_W (320 * EROW)
#define E_BUF_W (384 * EROW)
#define SMEM_BYTES_EMB (2 * E_BUF_W * 4)  // 110592 B

// ---------------------------------------------------------------------------
// Embed (tensor core, pipelined K): E[t][b][:] = inp[b,t,:] @ U / 16 + bias
// grid = (16 ntile, 256 mtile); mtile -> b = mt>>2, t0 = (mt&3)*128. M=128.
// 4 K-chunks of 64, double-buffered cp.async.  (verified in R14: ~155us)
// ---------------------------------------------------------------------------
__global__ void __launch_bounds__(NTHREADS, 2) embed_mma_kernel(
        const float* __restrict__ bias) {
    extern __shared__ __align__(16) uint32_t smw[];
    const int tid = threadIdx.x;
    const int wid = tid >> 5;
    const int lt  = tid & 31;
    const int g4  = lt >> 2;
    const int q4  = lt & 3;
    const int nb  = blockIdx.x;
    const int mt_idx = blockIdx.y;
    const int n0  = nb * NTILE;
    const int b   = mt_idx >> 2;
    const int t0  = (mt_idx & 3) << 7;
    const size_t row0 = (size_t)b * T_ + t0;

    const int m_base = (wid >> 1) * 32;
    const int n_base = (wid & 1) * 32;

    const int a_r  = lt & 15;
    const int a_cw = ((lt >> 4) & 1) * 4;
    const int b_r  = ((lt >> 4) & 1) * 8 + (lt & 7);
    const int b_cw = ((lt >> 3) & 1) * 4;

    uint32_t smem_b32 = (uint32_t)__cvta_generic_to_shared(smw);

    float acc[2][4][4];
    #pragma unroll
    for (int mt = 0; mt < 2; mt++)
        #pragma unroll
        for (int nt = 0; nt < 4; nt++)
            #pragma unroll
            for (int j = 0; j < 4; j++) acc[mt][nt][j] = 0.f;

    #define E_PREFETCH(c_, bw_)                                                \
    {                                                                          \
        const int i0 = (c_) * 64;                                             \
        const uint32_t bufb = smem_b32 + (bw_) * E_BUF_W * 4;                  \
        _Pragma("unroll")                                                      \
        for (int i = 0; i < 8; i++) {                                          \
            int idx = i * 256 + tid;                                           \
            int ch  = idx & 7;                                                 \
            int r   = (idx >> 3) & 127;                                        \
            int hl  = idx >> 10;                                               \
            const __nv_bfloat16* src = hl ? g_in_lo : g_in_hi;                 \
            uint32_t dst = bufb + ((hl ? EA_LO_W : EA_HI_W) + r * EROW + ch * 4) * 4; \
            const char* g = (const char*)(src + (row0 + r) * I_ + i0 + ch * 8);\
            asm volatile("cp.async.cg.shared.global [%0], [%1], 16;\n" :: "r"(dst), "l"(g)); \
        }                                                                      \
        _Pragma("unroll")                                                      \
        for (int i = 0; i < 4; i++) {                                          \
            int idx = i * 256 + tid;                                           \
            int ch  = idx & 7;                                                 \
            int r   = (idx >> 3) & 63;                                         \
            int hl  = idx >> 9;                                                \
            const __nv_bfloat16* src = hl ? g_Ut_lo : g_Ut_hi;                 \
            uint32_t dst = bufb + ((hl ? EB_LO_W : EB_HI_W) + r * EROW + ch * 4) * 4; \
            const char* g = (const char*)(src + (size_t)(n0 + r) * I_ + i0 + ch * 8); \
            asm volatile("cp.async.cg.shared.global [%0], [%1], 16;\n" :: "r"(dst), "l"(g)); \
        }                                                                      \
        asm volatile("cp.async.commit_group;\n");                              \
    }

    E_PREFETCH(0, 0);

    for (int c = 0; c < 4; c++) {
        const int buf = c & 1;
        if (c + 1 < 4) {
            E_PREFETCH(c + 1, (c + 1) & 1);
            asm volatile("cp.async.wait_group 1;\n");
        } else {
            asm volatile("cp.async.wait_group 0;\n");
        }
        __syncthreads();

        const uint32_t bufb = smem_b32 + buf * E_BUF_W * 4;
        #pragma unroll
        for (int kc = 0; kc < 4; kc++) {
            const int kw = kc * 8;
            uint32_t a_hi[2][4], a_lo[2][4], b_hi[2][4], b_lo[2][4];
            #pragma unroll
            for (int mt = 0; mt < 2; mt++) {
                int row = m_base + mt * 16 + a_r;
                ldm_x4(a_hi[mt], bufb + (EA_HI_W + row * EROW + kw + a_cw) * 4);
                ldm_x4(a_lo[mt], bufb + (EA_LO_W + row * EROW + kw + a_cw) * 4);
            }
            #pragma unroll
            for (int np = 0; np < 2; np++) {
                int row = n_base + np * 16 + b_r;
                ldm_x4(b_hi[np], bufb + (EB_HI_W + row * EROW + kw + b_cw) * 4);
                ldm_x4(b_lo[np], bufb + (EB_LO_W + row * EROW + kw + b_cw) * 4);
            }
            #pragma unroll
            for (int mt = 0; mt < 2; mt++)
                #pragma unroll
                for (int np = 0; np < 2; np++)
                    #pragma unroll
                    for (int h = 0; h < 2; h++) {
                        mma_bf16(acc[mt][np * 2 + h], a_hi[mt], &b_hi[np][h * 2]);
                        mma_bf16(acc[mt][np * 2 + h], a_hi[mt], &b_lo[np][h * 2]);
                        mma_bf16(acc[mt][np * 2 + h], a_lo[mt], &b_hi[np][h * 2]);
                    }
        }
        __syncthreads();
    }

    const float inv16 = 0.0625f;
    #pragma unroll
    for (int nt = 0; nt < 4; nt++) {
        const int C = n0 + n_base + nt * 8 + q4 * 2;
        float2 bv = *(const float2*)&bias[C];
        #pragma unroll
        for (int mt = 0; mt < 2; mt++) {
            const int R = m_base + mt * 16 + g4;
            float2 o0 = make_float2(acc[mt][nt][0] * inv16 + bv.x,
                                    acc[mt][nt][1] * inv16 + bv.y);
            float2 o1 = make_float2(acc[mt][nt][2] * inv16 + bv.x,
                                    acc[mt][nt][3] * inv16 + bv.y);
            *(float2*)&g_E[((size_t)(t0 + R) * B_ + b) * D_ + C]     = o0;
            *(float2*)&g_E[((size_t)(t0 + R + 8) * B_ + b) * D_ + C] = o1;
        }
    }
}

// ---------------------------------------------------------------------------
// s_0 = erf(E_first), split into bf16 hi/lo
// ---------------------------------------------------------------------------
__global__ void s0_kernel() {
    int idx = blockIdx.x * blockDim.x + threadIdx.x;
    int m = idx >> 10;
    int d = idx & 1023;
    float e = (m < B_) ? g_E[(size_t)0 * (B_ * D_) + m * D_ + d]
                       : g_E[(size_t)(T_ - 1) * (B_ * D_) + (m - B_) * D_ + d];
    float s = erff(e);
    __nv_bfloat16 h = __float2bfloat16(s);
    g_s_hi[idx] = h;
    g_s_lo[idx] = __float2bfloat16(s - __bfloat162float(h));
}

// ---------------------------------------------------------------------------
// Persistent recurrence kernel (R9 structure + K-chunked A-load/GEMM overlap):
// 2 independent chains on 256 co-resident CTAs.
// Per chain: 128 CTAs = 16 nb x 8 kb; per-CTA GEMM M=64, N=64, K=128.
// A loaded in two 64-col chunks (separate commit groups); GEMM on chunk 0
// starts while chunk 1 is still in flight. No change to barrier topology.
// ---------------------------------------------------------------------------
__global__ void __launch_bounds__(NTHREADS, 2) rnn_kernel() {
    extern __shared__ __align__(16) uint32_t smw[];
    const int tid   = threadIdx.x;
    const int wid   = tid >> 5;
    const int lt    = tid & 31;
    const int g4    = lt >> 2;
    const int q4    = lt & 3;
    const int bid   = blockIdx.x;
    const int chain = bid >> 7;          // 0 fwd, 1 bwd
    const int lbid  = bid & 127;
    const int nb    = lbid & 15;
    const int kb    = lbid >> 4;
    const int n0    = nb * NTILE;
    const int k0    = kb * KSLICE;
    const int srow0 = chain * B_;

    const int m_base = (wid >> 1) * 16;
    const int n_base = (wid & 1) * 32;

    const int a_r  = lt & 15;
    const int a_cw = ((lt >> 4) & 1) * 4;
    const int b_r  = ((lt >> 4) & 1) * 8 + (lt & 7);
    const int b_cw = ((lt >> 3) & 1) * 4;

    uint32_t smem_b32 = (uint32_t)__cvta_generic_to_shared(smw);

    // ---- Preload B = W^T slice (constant across steps) ----
    #pragma unroll
    for (int hl = 0; hl < 2; hl++) {
        const __nv_bfloat16* src = hl ? g_Wt_lo : g_Wt_hi;
        const int base_w = hl ? RB_LO_W : RB_HI_W;
        #pragma unroll
        for (int i = 0; i < 4; i++) {
            int idx = i * 256 + tid;
            int r   = idx >> 4;
            int ch  = idx & 15;
            uint32_t dst = smem_b32 + (base_w + r * SROW + ch * 4) * 4;
            const char* g = (const char*)(src + (size_t)(n0 + r) * D_ + k0) + ch * 16;
            asm volatile("cp.async.cg.shared.global [%0], [%1], 16;\n" :: "r"(dst), "l"(g));
        }
    }
    asm volatile("cp.async.commit_group;\n");
    asm volatile("cp.async.wait_group 0;\n");
    __syncthreads();

    // ldmatrix base addresses
    const uint32_t ah = smem_b32 + (RA_HI_W + (m_base + a_r) * SROW + a_cw) * 4;
    const uint32_t al = smem_b32 + (RA_LO_W + (m_base + a_r) * SROW + a_cw) * 4;
    uint32_t bh[2], bl[2];
    #pragma unroll
    for (int np = 0; np < 2; np++) {
        int row = n_base + np * 16 + b_r;
        bh[np] = smem_b32 + (RB_HI_W + row * SROW + b_cw) * 4;
        bl[np] = smem_b32 + (RB_LO_W + row * SROW + b_cw) * 4;
    }

    // reduce assignment: rows [nb*4,+4) x cols [kb*128,+128), float2/thread
    const int r_lrow = nb * 4 + (tid >> 6);
    const int r_d    = k0 + (tid & 63) * 2;

    // barrier counters (own 128B lines) — R9 layout
    unsigned* const c1_arr = &g_cnt[(chain * 2 + 0) * 256 + (nb >> 1) * 32];
    unsigned* const c1_wat = &g_cnt[(chain * 2 + 0) * 256 + kb * 32];
    unsigned* const c2     = &g_cnt[(chain * 2 + 1) * 256 + kb * 32];

    const __nv_bfloat16* const s_hi = g_s_hi + (size_t)srow0 * D_;
    const __nv_bfloat16* const s_lo = g_s_lo + (size_t)srow0 * D_;

    // A chunk load: 64 rows x cols [h*64, h*64+64), both planes; 4x16B/thread
    #define LOAD_A_CHUNK(h_)                                                   \
    {                                                                          \
        _Pragma("unroll")                                                      \
        for (int i = 0; i < 4; i++) {                                          \
            int idx = i * 256 + tid;          /* 0..1023 */                    \
            int ch  = idx & 7;                                                 \
            int r   = (idx >> 3) & 63;                                         \
            int hl  = idx >> 9;                                                \
            const __nv_bfloat16* src = hl ? s_lo : s_hi;                       \
            uint32_t dst = smem_b32 +                                          \
                ((hl ? RA_LO_W : RA_HI_W) + r * SROW + (h_) * 32 + ch * 4) * 4;\
            const char* g = (const char*)(src + (size_t)r * D_ + k0 + (h_) * 64) + ch * 16; \
            asm volatile("cp.async.cg.shared.global [%0], [%1], 16;\n" :: "r"(dst), "l"(g)); \
        }                                                                      \
        asm volatile("cp.async.commit_group;\n");                              \
    }

    for (int t = 0; t < T_ - 1; t++) {
        const unsigned tgt = 16u * (unsigned)(t + 1);

        // ---- Load A in two K-chunks (separate commit groups) ----
        LOAD_A_CHUNK(0);
        LOAD_A_CHUNK(1);

        // E prefetch for this step's reduce share
        const int te = chain ? (T_ - 2 - t) : (t + 1);
        const float2 e2 = *(const float2*)&g_E[((size_t)te * B_ + r_lrow) * D_ + r_d];

        float acc[4][4];
        #pragma unroll
        for (int j = 0; j < 4; j++)
            #pragma unroll
            for (int q = 0; q < 4; q++) acc[j][q] = 0.f;

        // ---- chunk 0 ready -> GEMM kc 0..3 while chunk 1 in flight ----
        asm volatile("cp.async.wait_group 1;\n");
        __syncthreads();
        #pragma unroll
        for (int kc = 0; kc < 4; kc++) {
            const uint32_t koff = kc * 32;
            uint32_t a_hi[4], a_lo[4], b_hi[2][4], b_lo[2][4];
            ldm_x4(a_hi, ah + koff);
            ldm_x4(a_lo, al + koff);
            #pragma unroll
            for (int np = 0; np < 2; np++) {
                ldm_x4(b_hi[np], bh[np] + koff);
                ldm_x4(b_lo[np], bl[np] + koff);
            }
            #pragma unroll
            for (int np = 0; np < 2; np++)
                #pragma unroll
                for (int h = 0; h < 2; h++) {
                    mma_bf16(acc[np * 2 + h], a_hi, &b_hi[np][h * 2]);
                    mma_bf16(acc[np * 2 + h], a_hi, &b_lo[np][h * 2]);
                    mma_bf16(acc[np * 2 + h], a_lo, &b_hi[np][h * 2]);
                }
        }

        // ---- chunk 1 ready -> GEMM kc 4..7 ----
        asm volatile("cp.async.wait_group 0;\n");
        __syncthreads();
        #pragma unroll
        for (int kc = 4; kc < 8; kc++) {
            const uint32_t koff = kc * 32;
            uint32_t a_hi[4], a_lo[4], b_hi[2][4], b_lo[2][4];
            ldm_x4(a_hi, ah + koff);
            ldm_x4(a_lo, al + koff);
            #pragma unroll
            for (int np = 0; np < 2; np++) {
                ldm_x4(b_hi[np], bh[np] + koff);
                ldm_x4(b_lo[np], bl[np] + koff);
            }
            #pragma unroll
            for (int np = 0; np < 2; np++)
                #pragma unroll
                for (int h = 0; h < 2; h++) {
                    mma_bf16(acc[np * 2 + h], a_hi, &b_hi[np][h * 2]);
                    mma_bf16(acc[np * 2 + h], a_hi, &b_lo[np][h * 2]);
                    mma_bf16(acc[np * 2 + h], a_lo, &b_hi[np][h * 2]);
                }
        }

        // ---- Write split-K partials ----
        {
            const int R = m_base + g4;
            #pragma unroll
            for (int j = 0; j < 4; j++) {
                const int C = n0 + n_base + j * 8 + q4 * 2;
                *(float2*)&g_part[chain][kb][R][C]     = make_float2(acc[j][0], acc[j][1]);
                *(float2*)&g_part[chain][kb][R + 8][C] = make_float2(acc[j][2], acc[j][3]);
            }
        }

        // ---- Barrier 1 (fan-in 16): partials for my reduce cols ready ----
        __syncthreads();
        if (tid == 0) {
            BAR_ARRIVE(c1_arr);
            BAR_SPIN(c1_wat, tgt);
        }
        __syncthreads();

        // ---- Reduce: c = sum/32, s = erf(E + c), split to bf16 hi/lo ----
        {
            float2 sum = {0.f, 0.f};
            #pragma unroll
            for (int kk = 0; kk < KSPLIT; kk++) {
                float2 p = __ldcg((const float2*)&g_part[chain][kk][r_lrow][r_d]);
                sum.x += p.x; sum.y += p.y;
            }
            float s0v = erff(e2.x + sum.x * 0.03125f);
            float s1v = erff(e2.y + sum.y * 0.03125f);
            __nv_bfloat16 h0 = __float2bfloat16(s0v);
            __nv_bfloat16 h1 = __float2bfloat16(s1v);
            __nv_bfloat16 l0 = __float2bfloat16(s0v - __bfloat162float(h0));
            __nv_bfloat16 l1 = __float2bfloat16(s1v - __bfloat162float(h1));
            uint32_t ph = ((uint32_t)__bfloat16_as_ushort(h1) << 16) | __bfloat16_as_ushort(h0);
            uint32_t pl = ((uint32_t)__bfloat16_as_ushort(l1) << 16) | __bfloat16_as_ushort(l0);
            *(uint32_t*)&g_s_hi[(size_t)(srow0 + r_lrow) * D_ + r_d] = ph;
            *(uint32_t*)&g_s_lo[(size_t)(srow0 + r_lrow) * D_ + r_d] = pl;
        }

        // ---- Barrier 2 (group of 16): s slice kb complete ----
        __syncthreads();
        if (tid == 0) {
            BAR_ARRIVE(c2);
            BAR_SPIN(c2, tgt);
        }
        __syncthreads();
    }
}

// ---------------------------------------------------------------------------
// Output head
// ---------------------------------------------------------------------------
__global__ void out_kernel(const float* __restrict__ v, float* __restrict__ out) {
    const int b   = blockIdx.x;
    const int tid = threadIdx.x;
    float sum = 0.f;
    for (int d = tid; d < D_; d += 256) {
        float sf = __bfloat162float(g_s_hi[b * D_ + d]) + __bfloat162float(g_s_lo[b * D_ + d]);
        float sb = __bfloat162float(g_s_hi[(B_ + b) * D_ + d]) + __bfloat162float(g_s_lo[(B_ + b) * D_ + d]);
        sum += sf * v[d] + sb * v[D_ + d];
    }
    __shared__ float red[256];
    red[tid] = sum;
    __syncthreads();
    #pragma unroll
    for (int s = 128; s > 0; s >>= 1) {
        if (tid < s) red[tid] += red[tid + s];
        __syncthreads();
    }
    if (tid == 0) out[b] = red[0] * 0.03125f;
}

// ---------------------------------------------------------------------------
// kernel_launch: graph-capturable (kernel launches only)
// ---------------------------------------------------------------------------
extern "C" void kernel_launch(void* const* d_in, const int* in_sizes, int n_in,
                              void* d_out, int out_size) {
    const float* inp  = (const float*)d_in[0];
    const float* W    = (const float*)d_in[1];
    const float* U    = (const float*)d_in[2];
    const float* bias = (const float*)d_in[3];
    const float* v    = (const float*)d_in[4];
    float* out        = (float*)d_out;

    static bool attr_set = false;
    if (!attr_set) {
        cudaFuncSetAttribute(rnn_kernel, cudaFuncAttributeMaxDynamicSharedMemorySize, SMEM_BYTES_RNN);
        cudaFuncSetAttribute(embed_mma_kernel, cudaFuncAttributeMaxDynamicSharedMemorySize, SMEM_BYTES_EMB);
        attr_set = true;
    }

    inp_split_kernel<<<(B_ * T_ * I_ / 4 + 255) / 256, 256>>>(inp);
    ut_split_kernel<<<D_, 256>>>(U);
    wt_split_kernel<<<D_, 256>>>(W);
    embed_mma_kernel<<<dim3(16, 256), NTHREADS, SMEM_BYTES_EMB>>>(bias);
    s0_kernel<<<512, 256>>>();
    rnn_kernel<<<256, NTHREADS, SMEM_BYTES_RNN>>>();
    out_kernel<<<B_, 256>>>(v, out);
}

// round 16
// speedup vs baseline: 1.0683x; 1.0045x over previous
#include <cuda_runtime.h>
#include <cuda_bf16.h>
#include <math.h>
#include <stdint.h>

// Problem constants
#define B_   64
#define T_   512
#define I_   256
#define D_   1024
#define M_   128
#define NTHREADS 256
#define KSPLIT 8
#define KSLICE 128
#define NTILE  64

// ---------------------------------------------------------------------------
// Device globals (allocation-free scratch)
// ---------------------------------------------------------------------------
__device__ float g_E[T_ * B_ * D_];                          // embed [t][b][d]
__device__ __align__(16) __nv_bfloat16 g_s_hi[M_ * D_];      // rows 0-63 fwd, 64-127 bwd
__device__ __align__(16) __nv_bfloat16 g_s_lo[M_ * D_];
__device__ __align__(16) __nv_bfloat16 g_Wt_hi[D_ * D_];     // W^T [n][k]
__device__ __align__(16) __nv_bfloat16 g_Wt_lo[D_ * D_];
__device__ __align__(16) __nv_bfloat16 g_in_hi[B_ * T_ * I_];
__device__ __align__(16) __nv_bfloat16 g_in_lo[B_ * T_ * I_];
__device__ __align__(16) __nv_bfloat16 g_Ut_hi[D_ * I_];
__device__ __align__(16) __nv_bfloat16 g_Ut_lo[D_ * I_];
// Compact per-CTA partial blocks: [chain][kb][nb][row 0..63][col 0..63]
__device__ float g_part[2][KSPLIT][16][64][64];
// counters: [chain][type(c1,c2)][8 groups][32-word pad]   (R9 layout)
#define NCNT (2 * 2 * 8 * 32)
__device__ unsigned g_cnt[NCNT];

// ---------------------------------------------------------------------------
// mma.sync bf16 + ldmatrix (sm_80 baseline)
// ---------------------------------------------------------------------------
__device__ __forceinline__ void mma_bf16(float* c, const uint32_t* a, const uint32_t* b) {
    asm volatile(
        "mma.sync.aligned.m16n8k16.row.col.f32.bf16.bf16.f32 "
        "{%0,%1,%2,%3}, {%4,%5,%6,%7}, {%8,%9}, {%0,%1,%2,%3};"
        : "+f"(c[0]), "+f"(c[1]), "+f"(c[2]), "+f"(c[3])
        : "r"(a[0]), "r"(a[1]), "r"(a[2]), "r"(a[3]), "r"(b[0]), "r"(b[1]));
}

__device__ __forceinline__ void ldm_x4(uint32_t* r, uint32_t saddr) {
    asm volatile(
        "ldmatrix.sync.aligned.m8n8.x4.shared.b16 {%0,%1,%2,%3}, [%4];"
        : "=r"(r[0]), "=r"(r[1]), "=r"(r[2]), "=r"(r[3]) : "r"(saddr));
}

#define BAR_ARRIVE(ptr) \
    asm volatile("red.release.gpu.global.add.u32 [%0], 1;" :: "l"(ptr) : "memory")

#define BAR_SPIN(ptr, tgt) do { \
    unsigned _v; \
    do { asm volatile("ld.acquire.gpu.global.u32 %0, [%1];" \
                      : "=r"(_v) : "l"(ptr) : "memory"); } while (_v < (tgt)); \
} while (0)

// ---------------------------------------------------------------------------
// Split kernels (one-time prep). inp_split also zeroes counters.
// ---------------------------------------------------------------------------
__global__ void inp_split_kernel(const float* __restrict__ inp) {
    if (blockIdx.x == 0) {
        for (int i = threadIdx.x; i < NCNT; i += blockDim.x) g_cnt[i] = 0;
    }
    int idx = blockIdx.x * blockDim.x + threadIdx.x;
    const int N4 = B_ * T_ * I_ / 4;
    if (idx >= N4) return;
    float4 a = ((const float4*)inp)[idx];
    __nv_bfloat16 h0 = __float2bfloat16(a.x), h1 = __float2bfloat16(a.y);
    __nv_bfloat16 h2 = __float2bfloat16(a.z), h3 = __float2bfloat16(a.w);
    __nv_bfloat16 l0 = __float2bfloat16(a.x - __bfloat162float(h0));
    __nv_bfloat16 l1 = __float2bfloat16(a.y - __bfloat162float(h1));
    __nv_bfloat16 l2 = __float2bfloat16(a.z - __bfloat162float(h2));
    __nv_bfloat16 l3 = __float2bfloat16(a.w - __bfloat162float(h3));
    uint2 ph, pl;
    ph.x = ((uint32_t)__bfloat16_as_ushort(h1) << 16) | __bfloat16_as_ushort(h0);
    ph.y = ((uint32_t)__bfloat16_as_ushort(h3) << 16) | __bfloat16_as_ushort(h2);
    pl.x = ((uint32_t)__bfloat16_as_ushort(l1) << 16) | __bfloat16_as_ushort(l0);
    pl.y = ((uint32_t)__bfloat16_as_ushort(l3) << 16) | __bfloat16_as_ushort(l2);
    *(uint2*)&g_in_hi[idx * 4] = ph;
    *(uint2*)&g_in_lo[idx * 4] = pl;
}

// merged U^T and W^T splits (grid = D_ blocks)
__global__ void uw_split_kernel(const float* __restrict__ U,
                                const float* __restrict__ W) {
    const int n = blockIdx.x;
    for (int i = threadIdx.x; i < I_; i += 256) {
        float u = U[(size_t)i * D_ + n];
        __nv_bfloat16 h = __float2bfloat16(u);
        g_Ut_hi[(size_t)n * I_ + i] = h;
        g_Ut_lo[(size_t)n * I_ + i] = __float2bfloat16(u - __bfloat162float(h));
    }
    for (int k = threadIdx.x; k < D_; k += 256) {
        float w = W[(size_t)k * D_ + n];
        __nv_bfloat16 h = __float2bfloat16(w);
        g_Wt_hi[(size_t)n * D_ + k] = h;
        g_Wt_lo[(size_t)n * D_ + k] = __float2bfloat16(w - __bfloat162float(h));
    }
}

// ---------------------------------------------------------------------------
// RNN smem layout: bf16 rows of 128 elems, stride 68 words (conflict-free)
// ---------------------------------------------------------------------------
#define SROW 68
#define RA_HI_W 0
#define RA_LO_W (64 * SROW)
#define RB_HI_W (128 * SROW)
#define RB_LO_W (192 * SROW)
#define SMEM_BYTES_RNN (256 * SROW * 4)   // 69632 B, occ 2

// ---------------------------------------------------------------------------
// Embed smem layout: K-chunks of 64 bf16 (128B rows, stride 36 words),
// 2 buffers for cp.async double-buffering. 110592 B total, occ 2.
// ---------------------------------------------------------------------------
#define EROW 36
#define EA_HI_W 0
#define EA_LO_W (128 * EROW)
#define EB_HI_W (256 * EROW)
#define EB_LO_W (320 * EROW)
#define E_BUF_W (384 * EROW)
#define SMEM_BYTES_EMB (2 * E_BUF_W * 4)  // 110592 B

// ---------------------------------------------------------------------------
// Embed (tensor core, pipelined K): E[t][b][:] = inp[b,t,:] @ U / 16 + bias
// (verified R14/R15: ~155us)
// ---------------------------------------------------------------------------
__global__ void __launch_bounds__(NTHREADS, 2) embed_mma_kernel(
        const float* __restrict__ bias) {
    extern __shared__ __align__(16) uint32_t smw[];
    const int tid = threadIdx.x;
    const int wid = tid >> 5;
    const int lt  = tid & 31;
    const int g4  = lt >> 2;
    const int q4  = lt & 3;
    const int nb  = blockIdx.x;
    const int mt_idx = blockIdx.y;
    const int n0  = nb * NTILE;
    const int b   = mt_idx >> 2;
    const int t0  = (mt_idx & 3) << 7;
    const size_t row0 = (size_t)b * T_ + t0;

    const int m_base = (wid >> 1) * 32;
    const int n_base = (wid & 1) * 32;

    const int a_r  = lt & 15;
    const int a_cw = ((lt >> 4) & 1) * 4;
    const int b_r  = ((lt >> 4) & 1) * 8 + (lt & 7);
    const int b_cw = ((lt >> 3) & 1) * 4;

    uint32_t smem_b32 = (uint32_t)__cvta_generic_to_shared(smw);

    float acc[2][4][4];
    #pragma unroll
    for (int mt = 0; mt < 2; mt++)
        #pragma unroll
        for (int nt = 0; nt < 4; nt++)
            #pragma unroll
            for (int j = 0; j < 4; j++) acc[mt][nt][j] = 0.f;

    #define E_PREFETCH(c_, bw_)                                                \
    {                                                                          \
        const int i0 = (c_) * 64;                                             \
        const uint32_t bufb = smem_b32 + (bw_) * E_BUF_W * 4;                  \
        _Pragma("unroll")                                                      \
        for (int i = 0; i < 8; i++) {                                          \
            int idx = i * 256 + tid;                                           \
            int ch  = idx & 7;                                                 \
            int r   = (idx >> 3) & 127;                                        \
            int hl  = idx >> 10;                                               \
            const __nv_bfloat16* src = hl ? g_in_lo : g_in_hi;                 \
            uint32_t dst = bufb + ((hl ? EA_LO_W : EA_HI_W) + r * EROW + ch * 4) * 4; \
            const char* g = (const char*)(src + (row0 + r) * I_ + i0 + ch * 8);\
            asm volatile("cp.async.cg.shared.global [%0], [%1], 16;\n" :: "r"(dst), "l"(g)); \
        }                                                                      \
        _Pragma("unroll")                                                      \
        for (int i = 0; i < 4; i++) {                                          \
            int idx = i * 256 + tid;                                           \
            int ch  = idx & 7;                                                 \
            int r   = (idx >> 3) & 63;                                         \
            int hl  = idx >> 9;                                                \
            const __nv_bfloat16* src = hl ? g_Ut_lo : g_Ut_hi;                 \
            uint32_t dst = bufb + ((hl ? EB_LO_W : EB_HI_W) + r * EROW + ch * 4) * 4; \
            const char* g = (const char*)(src + (size_t)(n0 + r) * I_ + i0 + ch * 8); \
            asm volatile("cp.async.cg.shared.global [%0], [%1], 16;\n" :: "r"(dst), "l"(g)); \
        }                                                                      \
        asm volatile("cp.async.commit_group;\n");                              \
    }

    E_PREFETCH(0, 0);

    for (int c = 0; c < 4; c++) {
        const int buf = c & 1;
        if (c + 1 < 4) {
            E_PREFETCH(c + 1, (c + 1) & 1);
            asm volatile("cp.async.wait_group 1;\n");
        } else {
            asm volatile("cp.async.wait_group 0;\n");
        }
        __syncthreads();

        const uint32_t bufb = smem_b32 + buf * E_BUF_W * 4;
        #pragma unroll
        for (int kc = 0; kc < 4; kc++) {
            const int kw = kc * 8;
            uint32_t a_hi[2][4], a_lo[2][4], b_hi[2][4], b_lo[2][4];
            #pragma unroll
            for (int mt = 0; mt < 2; mt++) {
                int row = m_base + mt * 16 + a_r;
                ldm_x4(a_hi[mt], bufb + (EA_HI_W + row * EROW + kw + a_cw) * 4);
                ldm_x4(a_lo[mt], bufb + (EA_LO_W + row * EROW + kw + a_cw) * 4);
            }
            #pragma unroll
            for (int np = 0; np < 2; np++) {
                int row = n_base + np * 16 + b_r;
                ldm_x4(b_hi[np], bufb + (EB_HI_W + row * EROW + kw + b_cw) * 4);
                ldm_x4(b_lo[np], bufb + (EB_LO_W + row * EROW + kw + b_cw) * 4);
            }
            #pragma unroll
            for (int mt = 0; mt < 2; mt++)
                #pragma unroll
                for (int np = 0; np < 2; np++)
                    #pragma unroll
                    for (int h = 0; h < 2; h++) {
                        mma_bf16(acc[mt][np * 2 + h], a_hi[mt], &b_hi[np][h * 2]);
                        mma_bf16(acc[mt][np * 2 + h], a_hi[mt], &b_lo[np][h * 2]);
                        mma_bf16(acc[mt][np * 2 + h], a_lo[mt], &b_hi[np][h * 2]);
                    }
        }
        __syncthreads();
    }

    const float inv16 = 0.0625f;
    #pragma unroll
    for (int nt = 0; nt < 4; nt++) {
        const int C = n0 + n_base + nt * 8 + q4 * 2;
        float2 bv = *(const float2*)&bias[C];
        #pragma unroll
        for (int mt = 0; mt < 2; mt++) {
            const int R = m_base + mt * 16 + g4;
            float2 o0 = make_float2(acc[mt][nt][0] * inv16 + bv.x,
                                    acc[mt][nt][1] * inv16 + bv.y);
            float2 o1 = make_float2(acc[mt][nt][2] * inv16 + bv.x,
                                    acc[mt][nt][3] * inv16 + bv.y);
            *(float2*)&g_E[((size_t)(t0 + R) * B_ + b) * D_ + C]     = o0;
            *(float2*)&g_E[((size_t)(t0 + R + 8) * B_ + b) * D_ + C] = o1;
        }
    }
}

// ---------------------------------------------------------------------------
// s_0 = erf(E_first), split into bf16 hi/lo
// ---------------------------------------------------------------------------
__global__ void s0_kernel() {
    int idx = blockIdx.x * blockDim.x + threadIdx.x;
    int m = idx >> 10;
    int d = idx & 1023;
    float e = (m < B_) ? g_E[(size_t)0 * (B_ * D_) + m * D_ + d]
                       : g_E[(size_t)(T_ - 1) * (B_ * D_) + (m - B_) * D_ + d];
    float s = erff(e);
    __nv_bfloat16 h = __float2bfloat16(s);
    g_s_hi[idx] = h;
    g_s_lo[idx] = __float2bfloat16(s - __bfloat162float(h));
}

// ---------------------------------------------------------------------------
// Persistent recurrence kernel (R15 + compact partial blocks):
// 2 independent chains on 256 co-resident CTAs.
// Per chain: 128 CTAs = 16 nb x 8 kb; per-CTA GEMM M=64, N=64, K=128.
// Partials: compact block g_part[chain][kb][nb][64][64].
// Reducer (nb,kb) -> rows [nb*4,+4) x cols [kb*128,+128): reads producer
// blocks nb' in {2kb, 2kb+1}.
// ---------------------------------------------------------------------------
__global__ void __launch_bounds__(NTHREADS, 2) rnn_kernel() {
    extern __shared__ __align__(16) uint32_t smw[];
    const int tid   = threadIdx.x;
    const int wid   = tid >> 5;
    const int lt    = tid & 31;
    const int g4    = lt >> 2;
    const int q4    = lt & 3;
    const int bid   = blockIdx.x;
    const int chain = bid >> 7;          // 0 fwd, 1 bwd
    const int lbid  = bid & 127;
    const int nb    = lbid & 15;
    const int kb    = lbid >> 4;
    const int n0    = nb * NTILE;
    const int k0    = kb * KSLICE;
    const int srow0 = chain * B_;

    const int m_base = (wid >> 1) * 16;
    const int n_base = (wid & 1) * 32;

    const int a_r  = lt & 15;
    const int a_cw = ((lt >> 4) & 1) * 4;
    const int b_r  = ((lt >> 4) & 1) * 8 + (lt & 7);
    const int b_cw = ((lt >> 3) & 1) * 4;

    uint32_t smem_b32 = (uint32_t)__cvta_generic_to_shared(smw);

    // ---- Preload B = W^T slice (constant across steps) ----
    #pragma unroll
    for (int hl = 0; hl < 2; hl++) {
        const __nv_bfloat16* src = hl ? g_Wt_lo : g_Wt_hi;
        const int base_w = hl ? RB_LO_W : RB_HI_W;
        #pragma unroll
        for (int i = 0; i < 4; i++) {
            int idx = i * 256 + tid;
            int r   = idx >> 4;
            int ch  = idx & 15;
            uint32_t dst = smem_b32 + (base_w + r * SROW + ch * 4) * 4;
            const char* g = (const char*)(src + (size_t)(n0 + r) * D_ + k0) + ch * 16;
            asm volatile("cp.async.cg.shared.global [%0], [%1], 16;\n" :: "r"(dst), "l"(g));
        }
    }
    asm volatile("cp.async.commit_group;\n");
    asm volatile("cp.async.wait_group 0;\n");
    __syncthreads();

    // ldmatrix base addresses
    const uint32_t ah = smem_b32 + (RA_HI_W + (m_base + a_r) * SROW + a_cw) * 4;
    const uint32_t al = smem_b32 + (RA_LO_W + (m_base + a_r) * SROW + a_cw) * 4;
    uint32_t bh[2], bl[2];
    #pragma unroll
    for (int np = 0; np < 2; np++) {
        int row = n_base + np * 16 + b_r;
        bh[np] = smem_b32 + (RB_HI_W + row * SROW + b_cw) * 4;
        bl[np] = smem_b32 + (RB_LO_W + row * SROW + b_cw) * 4;
    }

    // reduce assignment: rows [nb*4,+4) x cols [kb*128,+128), float2/thread
    const int r_lrow = nb * 4 + (tid >> 6);
    const int r_d    = k0 + (tid & 63) * 2;
    const int r_nbp  = 2 * kb + ((tid & 63) >> 5);     // producer block nb'
    const int r_cloc = (2 * (tid & 63)) & 63;          // col within block

    // barrier counters (own 128B lines) — R9 layout
    unsigned* const c1_arr = &g_cnt[(chain * 2 + 0) * 256 + (nb >> 1) * 32];
    unsigned* const c1_wat = &g_cnt[(chain * 2 + 0) * 256 + kb * 32];
    unsigned* const c2     = &g_cnt[(chain * 2 + 1) * 256 + kb * 32];

    const __nv_bfloat16* const s_hi = g_s_hi + (size_t)srow0 * D_;
    const __nv_bfloat16* const s_lo = g_s_lo + (size_t)srow0 * D_;

    // A chunk load: 64 rows x cols [h*64, h*64+64), both planes; 4x16B/thread
    #define LOAD_A_CHUNK(h_)                                                   \
    {                                                                          \
        _Pragma("unroll")                                                      \
        for (int i = 0; i < 4; i++) {                                          \
            int idx = i * 256 + tid;                                           \
            int ch  = idx & 7;                                                 \
            int r   = (idx >> 3) & 63;                                         \
            int hl  = idx >> 9;                                                \
            const __nv_bfloat16* src = hl ? s_lo : s_hi;                       \
            uint32_t dst = smem_b32 +                                          \
                ((hl ? RA_LO_W : RA_HI_W) + r * SROW + (h_) * 32 + ch * 4) * 4;\
            const char* g = (const char*)(src + (size_t)r * D_ + k0 + (h_) * 64) + ch * 16; \
            asm volatile("cp.async.cg.shared.global [%0], [%1], 16;\n" :: "r"(dst), "l"(g)); \
        }                                                                      \
        asm volatile("cp.async.commit_group;\n");                              \
    }

    for (int t = 0; t < T_ - 1; t++) {
        const unsigned tgt = 16u * (unsigned)(t + 1);

        // ---- Load A in two K-chunks (separate commit groups) ----
        LOAD_A_CHUNK(0);
        LOAD_A_CHUNK(1);

        // E prefetch for this step's reduce share
        const int te = chain ? (T_ - 2 - t) : (t + 1);
        const float2 e2 = *(const float2*)&g_E[((size_t)te * B_ + r_lrow) * D_ + r_d];

        float acc[4][4];
        #pragma unroll
        for (int j = 0; j < 4; j++)
            #pragma unroll
            for (int q = 0; q < 4; q++) acc[j][q] = 0.f;

        // ---- chunk 0 ready -> GEMM kc 0..3 while chunk 1 in flight ----
        asm volatile("cp.async.wait_group 1;\n");
        __syncthreads();
        #pragma unroll
        for (int kc = 0; kc < 4; kc++) {
            const uint32_t koff = kc * 32;
            uint32_t a_hi[4], a_lo[4], b_hi[2][4], b_lo[2][4];
            ldm_x4(a_hi, ah + koff);
            ldm_x4(a_lo, al + koff);
            #pragma unroll
            for (int np = 0; np < 2; np++) {
                ldm_x4(b_hi[np], bh[np] + koff);
                ldm_x4(b_lo[np], bl[np] + koff);
            }
            #pragma unroll
            for (int np = 0; np < 2; np++)
                #pragma unroll
                for (int h = 0; h < 2; h++) {
                    mma_bf16(acc[np * 2 + h], a_hi, &b_hi[np][h * 2]);
                    mma_bf16(acc[np * 2 + h], a_hi, &b_lo[np][h * 2]);
                    mma_bf16(acc[np * 2 + h], a_lo, &b_hi[np][h * 2]);
                }
        }

        // ---- chunk 1 ready -> GEMM kc 4..7 ----
        asm volatile("cp.async.wait_group 0;\n");
        __syncthreads();
        #pragma unroll
        for (int kc = 4; kc < 8; kc++) {
            const uint32_t koff = kc * 32;
            uint32_t a_hi[4], a_lo[4], b_hi[2][4], b_lo[2][4];
            ldm_x4(a_hi, ah + koff);
            ldm_x4(a_lo, al + koff);
            #pragma unroll
            for (int np = 0; np < 2; np++) {
                ldm_x4(b_hi[np], bh[np] + koff);
                ldm_x4(b_lo[np], bl[np] + koff);
            }
            #pragma unroll
            for (int np = 0; np < 2; np++)
                #pragma unroll
                for (int h = 0; h < 2; h++) {
                    mma_bf16(acc[np * 2 + h], a_hi, &b_hi[np][h * 2]);
                    mma_bf16(acc[np * 2 + h], a_hi, &b_lo[np][h * 2]);
                    mma_bf16(acc[np * 2 + h], a_lo, &b_hi[np][h * 2]);
                }
        }

        // ---- Write split-K partials (compact block, 256B row stride) ----
        {
            float* blk = &g_part[chain][kb][nb][0][0];
            const int R = m_base + g4;
            #pragma unroll
            for (int j = 0; j < 4; j++) {
                const int C = n_base + j * 8 + q4 * 2;
                *(float2*)&blk[R * 64 + C]       = make_float2(acc[j][0], acc[j][1]);
                *(float2*)&blk[(R + 8) * 64 + C] = make_float2(acc[j][2], acc[j][3]);
            }
        }

        // ---- Barrier 1 (fan-in 16): partials for my reduce cols ready ----
        __syncthreads();
        if (tid == 0) {
            BAR_ARRIVE(c1_arr);
            BAR_SPIN(c1_wat, tgt);
        }
        __syncthreads();

        // ---- Reduce: c = sum/32, s = erf(E + c), split to bf16 hi/lo ----
        {
            float2 sum = {0.f, 0.f};
            #pragma unroll
            for (int kk = 0; kk < KSPLIT; kk++) {
                float2 p = __ldcg((const float2*)&g_part[chain][kk][r_nbp][r_lrow][r_cloc]);
                sum.x += p.x; sum.y += p.y;
            }
            float s0v = erff(e2.x + sum.x * 0.03125f);
            float s1v = erff(e2.y + sum.y * 0.03125f);
            __nv_bfloat16 h0 = __float2bfloat16(s0v);
            __nv_bfloat16 h1 = __float2bfloat16(s1v);
            __nv_bfloat16 l0 = __float2bfloat16(s0v - __bfloat162float(h0));
            __nv_bfloat16 l1 = __float2bfloat16(s1v - __bfloat162float(h1));
            uint32_t ph = ((uint32_t)__bfloat16_as_ushort(h1) << 16) | __bfloat16_as_ushort(h0);
            uint32_t pl = ((uint32_t)__bfloat16_as_ushort(l1) << 16) | __bfloat16_as_ushort(l0);
            *(uint32_t*)&g_s_hi[(size_t)(srow0 + r_lrow) * D_ + r_d] = ph;
            *(uint32_t*)&g_s_lo[(size_t)(srow0 + r_lrow) * D_ + r_d] = pl;
        }

        // ---- Barrier 2 (group of 16): s slice kb complete ----
        __syncthreads();
        if (tid == 0) {
            BAR_ARRIVE(c2);
            BAR_SPIN(c2, tgt);
        }
        __syncthreads();
    }
}

// ---------------------------------------------------------------------------
// Output head
// ---------------------------------------------------------------------------
__global__ void out_kernel(const float* __restrict__ v, float* __restrict__ out) {
    const int b   = blockIdx.x;
    const int tid = threadIdx.x;
    float sum = 0.f;
    for (int d = tid; d < D_; d += 256) {
        float sf = __bfloat162float(g_s_hi[b * D_ + d]) + __bfloat162float(g_s_lo[b * D_ + d]);
        float sb = __bfloat162float(g_s_hi[(B_ + b) * D_ + d]) + __bfloat162float(g_s_lo[(B_ + b) * D_ + d]);
        sum += sf * v[d] + sb * v[D_ + d];
    }
    __shared__ float red[256];
    red[tid] = sum;
    __syncthreads();
    #pragma unroll
    for (int s = 128; s > 0; s >>= 1) {
        if (tid < s) red[tid] += red[tid + s];
        __syncthreads();
    }
    if (tid == 0) out[b] = red[0] * 0.03125f;
}

// ---------------------------------------------------------------------------
// kernel_launch: graph-capturable (kernel launches only)
// ---------------------------------------------------------------------------
extern "C" void kernel_launch(void* const* d_in, const int* in_sizes, int n_in,
                              void* d_out, int out_size) {
    const float* inp  = (const float*)d_in[0];
    const float* W    = (const float*)d_in[1];
    const float* U    = (const float*)d_in[2];
    const float* bias = (const float*)d_in[3];
    const float* v    = (const float*)d_in[4];
    float* out        = (float*)d_out;

    static bool attr_set = false;
    if (!attr_set) {
        cudaFuncSetAttribute(rnn_kernel, cudaFuncAttributeMaxDynamicSharedMemorySize, SMEM_BYTES_RNN);
        cudaFuncSetAttribute(embed_mma_kernel, cudaFuncAttributeMaxDynamicSharedMemorySize, SMEM_BYTES_EMB);
        attr_set = true;
    }

    inp_split_kernel<<<(B_ * T_ * I_ / 4 + 255) / 256, 256>>>(inp);
    uw_split_kernel<<<D_, 256>>>(U, W);
    embed_mma_kernel<<<dim3(16, 256), NTHREADS, SMEM_BYTES_EMB>>>(bias);
    s0_kernel<<<512, 256>>>();
    rnn_kernel<<<256, NTHREADS, SMEM_BYTES_RNN>>>();
    out_kernel<<<B_, 256>>>(v, out);
}

// round 17
// speedup vs baseline: 1.0700x; 1.0015x over previous
#include <cuda_runtime.h>
#include <cuda_bf16.h>
#include <math.h>
#include <stdint.h>

// Problem constants
#define B_   64
#define T_   512
#define I_   256
#define D_   1024
#define M_   128
#define NTHREADS 256
#define KSPLIT 8
#define KSLICE 128
#define NTILE  64

// ---------------------------------------------------------------------------
// Device globals (allocation-free scratch)
// ---------------------------------------------------------------------------
__device__ float g_E[T_ * B_ * D_];                          // embed [t][b][d]
__device__ __align__(16) __nv_bfloat16 g_s_hi[M_ * D_];      // rows 0-63 fwd, 64-127 bwd
__device__ __align__(16) __nv_bfloat16 g_s_lo[M_ * D_];
__device__ __align__(16) __nv_bfloat16 g_Wt_hi[D_ * D_];     // W^T [n][k]
__device__ __align__(16) __nv_bfloat16 g_Wt_lo[D_ * D_];
__device__ __align__(16) __nv_bfloat16 g_in_hi[B_ * T_ * I_];
__device__ __align__(16) __nv_bfloat16 g_in_lo[B_ * T_ * I_];
__device__ __align__(16) __nv_bfloat16 g_Ut_hi[D_ * I_];
__device__ __align__(16) __nv_bfloat16 g_Ut_lo[D_ * I_];
// Compact per-CTA partial blocks: [chain][kb][nb][row 0..63][col 0..63]
__device__ float g_part[2][KSPLIT][16][64][64];
// counters: [chain][type(c1,c2)][8 groups][32-word pad]
#define NCNT (2 * 2 * 8 * 32)
__device__ unsigned g_cnt[NCNT];

// ---------------------------------------------------------------------------
// mma.sync bf16 + ldmatrix (sm_80 baseline)
// ---------------------------------------------------------------------------
__device__ __forceinline__ void mma_bf16(float* c, const uint32_t* a, const uint32_t* b) {
    asm volatile(
        "mma.sync.aligned.m16n8k16.row.col.f32.bf16.bf16.f32 "
        "{%0,%1,%2,%3}, {%4,%5,%6,%7}, {%8,%9}, {%0,%1,%2,%3};"
        : "+f"(c[0]), "+f"(c[1]), "+f"(c[2]), "+f"(c[3])
        : "r"(a[0]), "r"(a[1]), "r"(a[2]), "r"(a[3]), "r"(b[0]), "r"(b[1]));
}

__device__ __forceinline__ void ldm_x4(uint32_t* r, uint32_t saddr) {
    asm volatile(
        "ldmatrix.sync.aligned.m8n8.x4.shared.b16 {%0,%1,%2,%3}, [%4];"
        : "=r"(r[0]), "=r"(r[1]), "=r"(r[2]), "=r"(r[3]) : "r"(saddr));
}

#define BAR_ARRIVE(ptr) \
    asm volatile("red.release.gpu.global.add.u32 [%0], 1;" :: "l"(ptr) : "memory")

#define BAR_SPIN(ptr, tgt) do { \
    unsigned _v; \
    do { asm volatile("ld.acquire.gpu.global.u32 %0, [%1];" \
                      : "=r"(_v) : "l"(ptr) : "memory"); } while (_v < (tgt)); \
} while (0)

// ---------------------------------------------------------------------------
// Split kernels (one-time prep). inp_split also zeroes counters.
// ---------------------------------------------------------------------------
__global__ void inp_split_kernel(const float* __restrict__ inp) {
    if (blockIdx.x == 0) {
        for (int i = threadIdx.x; i < NCNT; i += blockDim.x) g_cnt[i] = 0;
    }
    int idx = blockIdx.x * blockDim.x + threadIdx.x;
    const int N4 = B_ * T_ * I_ / 4;
    if (idx >= N4) return;
    float4 a = ((const float4*)inp)[idx];
    __nv_bfloat16 h0 = __float2bfloat16(a.x), h1 = __float2bfloat16(a.y);
    __nv_bfloat16 h2 = __float2bfloat16(a.z), h3 = __float2bfloat16(a.w);
    __nv_bfloat16 l0 = __float2bfloat16(a.x - __bfloat162float(h0));
    __nv_bfloat16 l1 = __float2bfloat16(a.y - __bfloat162float(h1));
    __nv_bfloat16 l2 = __float2bfloat16(a.z - __bfloat162float(h2));
    __nv_bfloat16 l3 = __float2bfloat16(a.w - __bfloat162float(h3));
    uint2 ph, pl;
    ph.x = ((uint32_t)__bfloat16_as_ushort(h1) << 16) | __bfloat16_as_ushort(h0);
    ph.y = ((uint32_t)__bfloat16_as_ushort(h3) << 16) | __bfloat16_as_ushort(h2);
    pl.x = ((uint32_t)__bfloat16_as_ushort(l1) << 16) | __bfloat16_as_ushort(l0);
    pl.y = ((uint32_t)__bfloat16_as_ushort(l3) << 16) | __bfloat16_as_ushort(l2);
    *(uint2*)&g_in_hi[idx * 4] = ph;
    *(uint2*)&g_in_lo[idx * 4] = pl;
}

// merged U^T and W^T splits (grid = D_ blocks)
__global__ void uw_split_kernel(const float* __restrict__ U,
                                const float* __restrict__ W) {
    const int n = blockIdx.x;
    for (int i = threadIdx.x; i < I_; i += 256) {
        float u = U[(size_t)i * D_ + n];
        __nv_bfloat16 h = __float2bfloat16(u);
        g_Ut_hi[(size_t)n * I_ + i] = h;
        g_Ut_lo[(size_t)n * I_ + i] = __float2bfloat16(u - __bfloat162float(h));
    }
    for (int k = threadIdx.x; k < D_; k += 256) {
        float w = W[(size_t)k * D_ + n];
        __nv_bfloat16 h = __float2bfloat16(w);
        g_Wt_hi[(size_t)n * D_ + k] = h;
        g_Wt_lo[(size_t)n * D_ + k] = __float2bfloat16(w - __bfloat162float(h));
    }
}

// ---------------------------------------------------------------------------
// RNN smem layout: bf16 rows of 128 elems, stride 68 words (conflict-free)
// ---------------------------------------------------------------------------
#define SROW 68
#define RA_HI_W 0
#define RA_LO_W (64 * SROW)
#define RB_HI_W (128 * SROW)
#define RB_LO_W (192 * SROW)
#define SMEM_BYTES_RNN (256 * SROW * 4)   // 69632 B, occ 2

// ---------------------------------------------------------------------------
// Embed smem layout (N=128 retile): K-chunks of 64 bf16 (stride 36 words),
// A 128 rows + B 128 rows per buffer, 2 buffers. 147456 B, occ 1.
// ---------------------------------------------------------------------------
#define EROW 36
#define EA_HI_W 0
#define EA_LO_W (128 * EROW)
#define EB_HI_W (256 * EROW)
#define EB_LO_W (384 * EROW)
#define E_BUF_W (512 * EROW)              // 18432 words per buffer
#define SMEM_BYTES_EMB (2 * E_BUF_W * 4)  // 147456 B

// ---------------------------------------------------------------------------
// Embed (tensor core, N=128 tile, pipelined K): E = inp @ U / 16 + bias
// grid = (8 ntile, 256 mtile); mtile -> b = mt>>2, t0 = (mt&3)*128.
// Per CTA: M=128, N=128, 4 K-chunks of 64, double-buffered cp.async.
// Warps: 2(M) x 4(N); warp tile 64(M) x 32(N).
// ---------------------------------------------------------------------------
__global__ void __launch_bounds__(NTHREADS, 1) embed_mma_kernel(
        const float* __restrict__ bias) {
    extern __shared__ __align__(16) uint32_t smw[];
    const int tid = threadIdx.x;
    const int wid = tid >> 5;
    const int lt  = tid & 31;
    const int g4  = lt >> 2;
    const int q4  = lt & 3;
    const int nb  = blockIdx.x;            // 0..7
    const int mt_idx = blockIdx.y;
    const int n0  = nb * 128;
    const int b   = mt_idx >> 2;
    const int t0  = (mt_idx & 3) << 7;
    const size_t row0 = (size_t)b * T_ + t0;

    const int m_base = (wid >> 2) * 64;    // 0, 64
    const int n_base = (wid & 3) * 32;     // 0, 32, 64, 96

    const int a_r  = lt & 15;
    const int a_cw = ((lt >> 4) & 1) * 4;
    const int b_r  = ((lt >> 4) & 1) * 8 + (lt & 7);
    const int b_cw = ((lt >> 3) & 1) * 4;

    uint32_t smem_b32 = (uint32_t)__cvta_generic_to_shared(smw);

    float acc[4][4][4];
    #pragma unroll
    for (int mt = 0; mt < 4; mt++)
        #pragma unroll
        for (int nt = 0; nt < 4; nt++)
            #pragma unroll
            for (int j = 0; j < 4; j++) acc[mt][nt][j] = 0.f;

    // prefetch K-chunk c into buffer bw: A 128x64x2 planes + B 128x64x2 planes
    #define E_PREFETCH(c_, bw_)                                                \
    {                                                                          \
        const int i0 = (c_) * 64;                                             \
        const uint32_t bufb = smem_b32 + (bw_) * E_BUF_W * 4;                  \
        _Pragma("unroll")                                                      \
        for (int i = 0; i < 8; i++) {                                          \
            int idx = i * 256 + tid;          /* 0..2047 */                    \
            int ch  = idx & 7;                                                 \
            int r   = (idx >> 3) & 127;                                        \
            int hl  = idx >> 10;                                               \
            const __nv_bfloat16* src = hl ? g_in_lo : g_in_hi;                 \
            uint32_t dst = bufb + ((hl ? EA_LO_W : EA_HI_W) + r * EROW + ch * 4) * 4; \
            const char* g = (const char*)(src + (row0 + r) * I_ + i0 + ch * 8);\
            asm volatile("cp.async.cg.shared.global [%0], [%1], 16;\n" :: "r"(dst), "l"(g)); \
        }                                                                      \
        _Pragma("unroll")                                                      \
        for (int i = 0; i < 8; i++) {                                          \
            int idx = i * 256 + tid;          /* 0..2047 */                    \
            int ch  = idx & 7;                                                 \
            int r   = (idx >> 3) & 127;                                        \
            int hl  = idx >> 10;                                               \
            const __nv_bfloat16* src = hl ? g_Ut_lo : g_Ut_hi;                 \
            uint32_t dst = bufb + ((hl ? EB_LO_W : EB_HI_W) + r * EROW + ch * 4) * 4; \
            const char* g = (const char*)(src + (size_t)(n0 + r) * I_ + i0 + ch * 8); \
            asm volatile("cp.async.cg.shared.global [%0], [%1], 16;\n" :: "r"(dst), "l"(g)); \
        }                                                                      \
        asm volatile("cp.async.commit_group;\n");                              \
    }

    E_PREFETCH(0, 0);

    for (int c = 0; c < 4; c++) {
        const int buf = c & 1;
        if (c + 1 < 4) {
            E_PREFETCH(c + 1, (c + 1) & 1);
            asm volatile("cp.async.wait_group 1;\n");
        } else {
            asm volatile("cp.async.wait_group 0;\n");
        }
        __syncthreads();

        const uint32_t bufb = smem_b32 + buf * E_BUF_W * 4;
        #pragma unroll
        for (int kc = 0; kc < 4; kc++) {
            const int kw = kc * 8;
            uint32_t a_hi[4][4], a_lo[4][4], b_hi[2][4], b_lo[2][4];
            #pragma unroll
            for (int mt = 0; mt < 4; mt++) {
                int row = m_base + mt * 16 + a_r;
                ldm_x4(a_hi[mt], bufb + (EA_HI_W + row * EROW + kw + a_cw) * 4);
                ldm_x4(a_lo[mt], bufb + (EA_LO_W + row * EROW + kw + a_cw) * 4);
            }
            #pragma unroll
            for (int np = 0; np < 2; np++) {
                int row = n_base + np * 16 + b_r;
                ldm_x4(b_hi[np], bufb + (EB_HI_W + row * EROW + kw + b_cw) * 4);
                ldm_x4(b_lo[np], bufb + (EB_LO_W + row * EROW + kw + b_cw) * 4);
            }
            #pragma unroll
            for (int mt = 0; mt < 4; mt++)
                #pragma unroll
                for (int np = 0; np < 2; np++)
                    #pragma unroll
                    for (int h = 0; h < 2; h++) {
                        mma_bf16(acc[mt][np * 2 + h], a_hi[mt], &b_hi[np][h * 2]);
                        mma_bf16(acc[mt][np * 2 + h], a_hi[mt], &b_lo[np][h * 2]);
                        mma_bf16(acc[mt][np * 2 + h], a_lo[mt], &b_hi[np][h * 2]);
                    }
        }
        __syncthreads();
    }

    const float inv16 = 0.0625f;
    #pragma unroll
    for (int nt = 0; nt < 4; nt++) {
        const int C = n0 + n_base + nt * 8 + q4 * 2;
        float2 bv = *(const float2*)&bias[C];
        #pragma unroll
        for (int mt = 0; mt < 4; mt++) {
            const int R = m_base + mt * 16 + g4;
            float2 o0 = make_float2(acc[mt][nt][0] * inv16 + bv.x,
                                    acc[mt][nt][1] * inv16 + bv.y);
            float2 o1 = make_float2(acc[mt][nt][2] * inv16 + bv.x,
                                    acc[mt][nt][3] * inv16 + bv.y);
            *(float2*)&g_E[((size_t)(t0 + R) * B_ + b) * D_ + C]     = o0;
            *(float2*)&g_E[((size_t)(t0 + R + 8) * B_ + b) * D_ + C] = o1;
        }
    }
}

// ---------------------------------------------------------------------------
// s_0 = erf(E_first), split into bf16 hi/lo
// ---------------------------------------------------------------------------
__global__ void s0_kernel() {
    int idx = blockIdx.x * blockDim.x + threadIdx.x;
    int m = idx >> 10;
    int d = idx & 1023;
    float e = (m < B_) ? g_E[(size_t)0 * (B_ * D_) + m * D_ + d]
                       : g_E[(size_t)(T_ - 1) * (B_ * D_) + (m - B_) * D_ + d];
    float s = erff(e);
    __nv_bfloat16 h = __float2bfloat16(s);
    g_s_hi[idx] = h;
    g_s_lo[idx] = __float2bfloat16(s - __bfloat162float(h));
}

// ---------------------------------------------------------------------------
// Persistent recurrence kernel (R16, unchanged — best verified):
// 2 independent chains on 256 co-resident CTAs.
// ---------------------------------------------------------------------------
__global__ void __launch_bounds__(NTHREADS, 2) rnn_kernel() {
    extern __shared__ __align__(16) uint32_t smw[];
    const int tid   = threadIdx.x;
    const int wid   = tid >> 5;
    const int lt    = tid & 31;
    const int g4    = lt >> 2;
    const int q4    = lt & 3;
    const int bid   = blockIdx.x;
    const int chain = bid >> 7;
    const int lbid  = bid & 127;
    const int nb    = lbid & 15;
    const int kb    = lbid >> 4;
    const int n0    = nb * NTILE;
    const int k0    = kb * KSLICE;
    const int srow0 = chain * B_;

    const int m_base = (wid >> 1) * 16;
    const int n_base = (wid & 1) * 32;

    const int a_r  = lt & 15;
    const int a_cw = ((lt >> 4) & 1) * 4;
    const int b_r  = ((lt >> 4) & 1) * 8 + (lt & 7);
    const int b_cw = ((lt >> 3) & 1) * 4;

    uint32_t smem_b32 = (uint32_t)__cvta_generic_to_shared(smw);

    // ---- Preload B = W^T slice (constant across steps) ----
    #pragma unroll
    for (int hl = 0; hl < 2; hl++) {
        const __nv_bfloat16* src = hl ? g_Wt_lo : g_Wt_hi;
        const int base_w = hl ? RB_LO_W : RB_HI_W;
        #pragma unroll
        for (int i = 0; i < 4; i++) {
            int idx = i * 256 + tid;
            int r   = idx >> 4;
            int ch  = idx & 15;
            uint32_t dst = smem_b32 + (base_w + r * SROW + ch * 4) * 4;
            const char* g = (const char*)(src + (size_t)(n0 + r) * D_ + k0) + ch * 16;
            asm volatile("cp.async.cg.shared.global [%0], [%1], 16;\n" :: "r"(dst), "l"(g));
        }
    }
    asm volatile("cp.async.commit_group;\n");
    asm volatile("cp.async.wait_group 0;\n");
    __syncthreads();

    const uint32_t ah = smem_b32 + (RA_HI_W + (m_base + a_r) * SROW + a_cw) * 4;
    const uint32_t al = smem_b32 + (RA_LO_W + (m_base + a_r) * SROW + a_cw) * 4;
    uint32_t bh[2], bl[2];
    #pragma unroll
    for (int np = 0; np < 2; np++) {
        int row = n_base + np * 16 + b_r;
        bh[np] = smem_b32 + (RB_HI_W + row * SROW + b_cw) * 4;
        bl[np] = smem_b32 + (RB_LO_W + row * SROW + b_cw) * 4;
    }

    const int r_lrow = nb * 4 + (tid >> 6);
    const int r_d    = k0 + (tid & 63) * 2;
    const int r_nbp  = 2 * kb + ((tid & 63) >> 5);
    const int r_cloc = (2 * (tid & 63)) & 63;

    unsigned* const c1_arr = &g_cnt[(chain * 2 + 0) * 256 + (nb >> 1) * 32];
    unsigned* const c1_wat = &g_cnt[(chain * 2 + 0) * 256 + kb * 32];
    unsigned* const c2     = &g_cnt[(chain * 2 + 1) * 256 + kb * 32];

    const __nv_bfloat16* const s_hi = g_s_hi + (size_t)srow0 * D_;
    const __nv_bfloat16* const s_lo = g_s_lo + (size_t)srow0 * D_;

    #define LOAD_A_CHUNK(h_)                                                   \
    {                                                                          \
        _Pragma("unroll")                                                      \
        for (int i = 0; i < 4; i++) {                                          \
            int idx = i * 256 + tid;                                           \
            int ch  = idx & 7;                                                 \
            int r   = (idx >> 3) & 63;                                         \
            int hl  = idx >> 9;                                                \
            const __nv_bfloat16* src = hl ? s_lo : s_hi;                       \
            uint32_t dst = smem_b32 +                                          \
                ((hl ? RA_LO_W : RA_HI_W) + r * SROW + (h_) * 32 + ch * 4) * 4;\
            const char* g = (const char*)(src + (size_t)r * D_ + k0 + (h_) * 64) + ch * 16; \
            asm volatile("cp.async.cg.shared.global [%0], [%1], 16;\n" :: "r"(dst), "l"(g)); \
        }                                                                      \
        asm volatile("cp.async.commit_group;\n");                              \
    }

    for (int t = 0; t < T_ - 1; t++) {
        const unsigned tgt = 16u * (unsigned)(t + 1);

        LOAD_A_CHUNK(0);
        LOAD_A_CHUNK(1);

        const int te = chain ? (T_ - 2 - t) : (t + 1);
        const float2 e2 = *(const float2*)&g_E[((size_t)te * B_ + r_lrow) * D_ + r_d];

        float acc[4][4];
        #pragma unroll
        for (int j = 0; j < 4; j++)
            #pragma unroll
            for (int q = 0; q < 4; q++) acc[j][q] = 0.f;

        asm volatile("cp.async.wait_group 1;\n");
        __syncthreads();
        #pragma unroll
        for (int kc = 0; kc < 4; kc++) {
            const uint32_t koff = kc * 32;
            uint32_t a_hi[4], a_lo[4], b_hi[2][4], b_lo[2][4];
            ldm_x4(a_hi, ah + koff);
            ldm_x4(a_lo, al + koff);
            #pragma unroll
            for (int np = 0; np < 2; np++) {
                ldm_x4(b_hi[np], bh[np] + koff);
                ldm_x4(b_lo[np], bl[np] + koff);
            }
            #pragma unroll
            for (int np = 0; np < 2; np++)
                #pragma unroll
                for (int h = 0; h < 2; h++) {
                    mma_bf16(acc[np * 2 + h], a_hi, &b_hi[np][h * 2]);
                    mma_bf16(acc[np * 2 + h], a_hi, &b_lo[np][h * 2]);
                    mma_bf16(acc[np * 2 + h], a_lo, &b_hi[np][h * 2]);
                }
        }

        asm volatile("cp.async.wait_group 0;\n");
        __syncthreads();
        #pragma unroll
        for (int kc = 4; kc < 8; kc++) {
            const uint32_t koff = kc * 32;
            uint32_t a_hi[4], a_lo[4], b_hi[2][4], b_lo[2][4];
            ldm_x4(a_hi, ah + koff);
            ldm_x4(a_lo, al + koff);
            #pragma unroll
            for (int np = 0; np < 2; np++) {
                ldm_x4(b_hi[np], bh[np] + koff);
                ldm_x4(b_lo[np], bl[np] + koff);
            }
            #pragma unroll
            for (int np = 0; np < 2; np++)
                #pragma unroll
                for (int h = 0; h < 2; h++) {
                    mma_bf16(acc[np * 2 + h], a_hi, &b_hi[np][h * 2]);
                    mma_bf16(acc[np * 2 + h], a_hi, &b_lo[np][h * 2]);
                    mma_bf16(acc[np * 2 + h], a_lo, &b_hi[np][h * 2]);
                }
        }

        {
            float* blk = &g_part[chain][kb][nb][0][0];
            const int R = m_base + g4;
            #pragma unroll
            for (int j = 0; j < 4; j++) {
                const int C = n_base + j * 8 + q4 * 2;
                *(float2*)&blk[R * 64 + C]       = make_float2(acc[j][0], acc[j][1]);
                *(float2*)&blk[(R + 8) * 64 + C] = make_float2(acc[j][2], acc[j][3]);
            }
        }

        __syncthreads();
        if (tid == 0) {
            BAR_ARRIVE(c1_arr);
            BAR_SPIN(c1_wat, tgt);
        }
        __syncthreads();

        {
            float2 sum = {0.f, 0.f};
            #pragma unroll
            for (int kk = 0; kk < KSPLIT; kk++) {
                float2 p = __ldcg((const float2*)&g_part[chain][kk][r_nbp][r_lrow][r_cloc]);
                sum.x += p.x; sum.y += p.y;
            }
            float s0v = erff(e2.x + sum.x * 0.03125f);
            float s1v = erff(e2.y + sum.y * 0.03125f);
            __nv_bfloat16 h0 = __float2bfloat16(s0v);
            __nv_bfloat16 h1 = __float2bfloat16(s1v);
            __nv_bfloat16 l0 = __float2bfloat16(s0v - __bfloat162float(h0));
            __nv_bfloat16 l1 = __float2bfloat16(s1v - __bfloat162float(h1));
            uint32_t ph = ((uint32_t)__bfloat16_as_ushort(h1) << 16) | __bfloat16_as_ushort(h0);
            uint32_t pl = ((uint32_t)__bfloat16_as_ushort(l1) << 16) | __bfloat16_as_ushort(l0);
            *(uint32_t*)&g_s_hi[(size_t)(srow0 + r_lrow) * D_ + r_d] = ph;
            *(uint32_t*)&g_s_lo[(size_t)(srow0 + r_lrow) * D_ + r_d] = pl;
        }

        __syncthreads();
        if (tid == 0) {
            BAR_ARRIVE(c2);
            BAR_SPIN(c2, tgt);
        }
        __syncthreads();
    }
}

// ---------------------------------------------------------------------------
// Output head
// ---------------------------------------------------------------------------
__global__ void out_kernel(const float* __restrict__ v, float* __restrict__ out) {
    const int b   = blockIdx.x;
    const int tid = threadIdx.x;
    float sum = 0.f;
    for (int d = tid; d < D_; d += 256) {
        float sf = __bfloat162float(g_s_hi[b * D_ + d]) + __bfloat162float(g_s_lo[b * D_ + d]);
        float sb = __bfloat162float(g_s_hi[(B_ + b) * D_ + d]) + __bfloat162float(g_s_lo[(B_ + b) * D_ + d]);
        sum += sf * v[d] + sb * v[D_ + d];
    }
    __shared__ float red[256];
    red[tid] = sum;
    __syncthreads();
    #pragma unroll
    for (int s = 128; s > 0; s >>= 1) {
        if (tid < s) red[tid] += red[tid + s];
        __syncthreads();
    }
    if (tid == 0) out[b] = red[0] * 0.03125f;
}

// ---------------------------------------------------------------------------
// kernel_launch: graph-capturable (kernel launches only)
// ---------------------------------------------------------------------------
extern "C" void kernel_launch(void* const* d_in, const int* in_sizes, int n_in,
                              void* d_out, int out_size) {
    const float* inp  = (const float*)d_in[0];
    const float* W    = (const float*)d_in[1];
    const float* U    = (const float*)d_in[2];
    const float* bias = (const float*)d_in[3];
    const float* v    = (const float*)d_in[4];
    float* out        = (float*)d_out;

    static bool attr_set = false;
    if (!attr_set) {
        cudaFuncSetAttribute(rnn_kernel, cudaFuncAttributeMaxDynamicSharedMemorySize, SMEM_BYTES_RNN);
        cudaFuncSetAttribute(embed_mma_kernel, cudaFuncAttributeMaxDynamicSharedMemorySize, SMEM_BYTES_EMB);
        attr_set = true;
    }

    inp_split_kernel<<<(B_ * T_ * I_ / 4 + 255) / 256, 256>>>(inp);
    uw_split_kernel<<<D_, 256>>>(U, W);
    embed_mma_kernel<<<dim3(8, 256), NTHREADS, SMEM_BYTES_EMB>>>(bias);
    s0_kernel<<<512, 256>>>();
    rnn_kernel<<<256, NTHREADS, SMEM_BYTES_RNN>>>();
    out_kernel<<<B_, 256>>>(v, out);
}